// round 14
// baseline (speedup 1.0000x reference)
#include <cuda_runtime.h>
#include <cuda_bf16.h>
#include <cstdint>
#include <math.h>

#define NBATCH 4
#define CH     256
#define NPIX   4096
#define KD     32
#define NZ     8   // 2 branches x 4 batches

// ---- scratch (module-load allocated; no runtime alloc) ----
__device__ __nv_bfloat16 g_fT[NZ][NPIX][KD];         // f^T : [n][k] bf16
__device__ __nv_bfloat16 g_gT[NZ][NPIX][KD];         // g^T : [m][k] bf16
__device__ float         g_invsum[NZ][NPIX];         // 1 / softmax row sum (shifted)
__device__ __nv_bfloat16 g_Xt[NZ][NPIX][CH];         // x^T : [n][c] bf16
__device__ __nv_bfloat16 g_Wb[2][CH][CH];            // h weights, bf16
__device__ __nv_bfloat16 g_Wfg[2*KD][CH];            // stacked [f_w; g_w], bf16
__device__ __nv_bfloat16 g_Hb[NZ][CH][NPIX];         // h projection (invsum-scaled), bf16
__device__ __nv_bfloat16 g_Pt[NZ][NPIX][NPIX];       // unnormalized P^T bf16: Pt[m][n]

// dynamic tile counters (reset by prep each launch)
__device__ unsigned int g_ctr_out;
__device__ unsigned int g_ctr_sm;
__device__ unsigned int g_ctr_ph;

__device__ __forceinline__ uint32_t smem_u32(const void* p) {
    uint32_t a;
    asm("{ .reg .u64 t; cvta.to.shared.u64 t, %1; cvt.u32.u64 %0, t; }" : "=r"(a) : "l"(p));
    return a;
}

__device__ __forceinline__ float ex2f(float x) {
    float r;
    asm("ex2.approx.f32 %0, %1;" : "=f"(r) : "f"(x));
    return r;
}

#define CP_ASYNC16(dst, src) \
    asm volatile("cp.async.cg.shared.global [%0], [%1], 16;" :: "r"(dst), "l"(src))
#define CP_ASYNC_COMMIT() asm volatile("cp.async.commit_group;" ::: "memory")
#define CP_ASYNC_WAIT_1() asm volatile("cp.async.wait_group 1;" ::: "memory")
#define CP_ASYNC_WAIT_0() asm volatile("cp.async.wait_group 0;" ::: "memory")

#define LDSM_X4(r0,r1,r2,r3,addr) \
    asm volatile("ldmatrix.sync.aligned.m8n8.x4.shared.b16 {%0,%1,%2,%3}, [%4];" \
        : "=r"(r0), "=r"(r1), "=r"(r2), "=r"(r3) : "r"(addr))

#define STSM_X2_TRANS(addr, r0, r1) \
    asm volatile("stmatrix.sync.aligned.m8n8.x2.trans.shared.b16 [%0], {%1, %2};" \
        :: "r"(addr), "r"(r0), "r"(r1) : "memory")

#define MMA_BF16(c0,c1,c2,c3,a0,a1,a2,a3,b0,b1) \
    asm volatile("mma.sync.aligned.m16n8k16.row.col.f32.bf16.bf16.f32 " \
        "{%0,%1,%2,%3}, {%4,%5,%6,%7}, {%8,%9}, {%0,%1,%2,%3};" \
        : "+f"(c0), "+f"(c1), "+f"(c2), "+f"(c3) \
        : "r"(a0), "r"(a1), "r"(a2), "r"(a3), "r"(b0), "r"(b1))

// =====================================================================
// Kernel P (merged prep): xt transpose (2048 blocks) + weight convert
// (32 blocks) + counter reset.
// =====================================================================
#define XT_BLKS 2048
#define WC_BLKS 32

__global__ __launch_bounds__(256) void prep_kernel(
    const float* __restrict__ x1, const float* __restrict__ x2,
    const float* __restrict__ f_w, const float* __restrict__ g_w,
    const float* __restrict__ h1w, const float* __restrict__ h2w)
{
    const int bx = blockIdx.x;
    const int tid = threadIdx.x;

    if (bx < XT_BLKS) {
        const int z  = bx >> 8;
        const int ct = (bx >> 6) & 3;
        const int nt = bx & 63;
        const int br = z >> 2, b = z & 3;
        const float* X = (br ? x2 : x1) + (size_t)b * CH * NPIX;
        const int n0 = nt * 64;
        const int c0 = ct * 64;

        __shared__ unsigned short t[64][66];
        const int rr = tid >> 4;
        const int c4 = (tid & 15) * 4;

#pragma unroll
        for (int p=0;p<4;p++){
            const int crow = rr + p*16;
            const float4 v = *reinterpret_cast<const float4*>(
                &X[(size_t)(c0 + crow) * NPIX + n0 + c4]);
            t[crow][c4+0] = __bfloat16_as_ushort(__float2bfloat16(v.x));
            t[crow][c4+1] = __bfloat16_as_ushort(__float2bfloat16(v.y));
            t[crow][c4+2] = __bfloat16_as_ushort(__float2bfloat16(v.z));
            t[crow][c4+3] = __bfloat16_as_ushort(__float2bfloat16(v.w));
        }
        __syncthreads();

#pragma unroll
        for (int p=0;p<4;p++){
            const int nrow = rr + p*16;
            uint2 u;
            u.x = (uint32_t)t[c4+0][nrow] | ((uint32_t)t[c4+1][nrow] << 16);
            u.y = (uint32_t)t[c4+2][nrow] | ((uint32_t)t[c4+3][nrow] << 16);
            *reinterpret_cast<uint2*>(&g_Xt[z][n0 + nrow][c0 + c4]) = u;
        }
    } else {
        const int blk = bx - XT_BLKS;
        if (blk == 0 && tid == 0) {
            g_ctr_out = 0; g_ctr_sm = 0; g_ctr_ph = 0;
        }
        const int idx = (blk * 256 + tid) * 8;
#pragma unroll
        for (int w = 0; w < 2; ++w) {
            const float* src = (w ? h2w : h1w) + idx;
            __nv_bfloat16* dst = &g_Wb[w][0][0] + idx;
#pragma unroll
            for (int j = 0; j < 2; ++j) {
                const float4 v = *reinterpret_cast<const float4*>(src + j*4);
                __nv_bfloat162 p0 = __float22bfloat162_rn(make_float2(v.x, v.y));
                __nv_bfloat162 p1 = __float22bfloat162_rn(make_float2(v.z, v.w));
                uint2 u;
                u.x = reinterpret_cast<uint32_t&>(p0);
                u.y = reinterpret_cast<uint32_t&>(p1);
                *reinterpret_cast<uint2*>(dst + j*4) = u;
            }
        }
        const int fgIdx = blk * 256 + tid;   // 0..8191
        if (fgIdx < KD * CH) {
            (&g_Wfg[0][0])[fgIdx]  = __float2bfloat16(f_w[fgIdx]);
            (&g_Wfg[KD][0])[fgIdx] = __float2bfloat16(g_w[fgIdx]);
        }
    }
}

// =====================================================================
// Kernel 1: fused f/g projection via HMMA from g_Xt.  (frozen)
// =====================================================================
#define FG_LDA   136
#define FG_AST   (64*FG_LDA*2)
#define FG_BST   (128*FG_LDA*2)
#define FG_STG   (FG_AST + FG_BST)
#define FG_SMEM  (2*FG_STG)

__global__ void __launch_bounds__(128, 2) proj_fg_mma_kernel(
    const float* __restrict__ f_b, const float* __restrict__ g_b)
{
    extern __shared__ char smf[];
    const uint32_t smBase = smem_u32(smf);

    const int tid = threadIdx.x;
    const int wid = tid >> 5, lane = tid & 31;
    const int z = blockIdx.y;
    const int nBase = blockIdx.x * 128;

    const int arow = tid >> 1;
    const int ahalf = (tid & 1) * 128;
    const char* gA = (const char*)&g_Wfg[arow][0] + ahalf;
    const uint32_t dA = (uint32_t)(arow * (FG_LDA*2) + ahalf);
    const char* gB = (const char*)&g_Xt[z][nBase + tid][0];
    const uint32_t dB = FG_AST + (uint32_t)(tid * (FG_LDA*2));

#pragma unroll
    for (int st = 0; st < 2; ++st) {
        const uint32_t slot = smBase + (uint32_t)st * FG_STG;
        const char* sa = gA + (size_t)st * 256;
        const char* sb = gB + (size_t)st * 256;
#pragma unroll
        for (int j=0;j<8;j++)  CP_ASYNC16(slot + dA + j*16, sa + j*16);
#pragma unroll
        for (int j=0;j<16;j++) CP_ASYNC16(slot + dB + j*16, sb + j*16);
        CP_ASYNC_COMMIT();
    }

    const int warpN = wid;
    const int lm  = lane & 15;
    const int aco = (lane >= 16) ? 8 : 0;
    uint32_t aOff[4];
#pragma unroll
    for (int mt=0; mt<4; mt++)
        aOff[mt] = (uint32_t)(((mt*16 + lm)*FG_LDA + aco)*2);
    const int bro = (lane & 7) + ((lane >= 16) ? 8 : 0);
    const int bco = (lane & 8) ? 8 : 0;
    uint32_t bOffA[2];
#pragma unroll
    for (int p=0; p<2; p++)
        bOffA[p] = FG_AST + (uint32_t)(((warpN*32 + p*16 + bro)*FG_LDA + bco)*2);

    float acc[4][4][4];
#pragma unroll
    for (int i=0;i<4;i++)
#pragma unroll
        for (int j=0;j<4;j++)
#pragma unroll
            for (int k=0;k<4;k++) acc[i][j][k] = 0.f;

#pragma unroll
    for (int st = 0; st < 2; ++st) {
        if (st == 0) CP_ASYNC_WAIT_1(); else CP_ASYNC_WAIT_0();
        __syncthreads();
        const uint32_t slot = smBase + (uint32_t)st * FG_STG;
#pragma unroll
        for (int ks = 0; ks < 8; ++ks) {
            uint32_t a[4][4];
#pragma unroll
            for (int mt=0; mt<4; mt++)
                LDSM_X4(a[mt][0], a[mt][1], a[mt][2], a[mt][3],
                        slot + aOff[mt] + ks*32);
            uint32_t bb[2][4];
#pragma unroll
            for (int p=0; p<2; p++)
                LDSM_X4(bb[p][0], bb[p][1], bb[p][2], bb[p][3],
                        slot + bOffA[p] + ks*32);
#pragma unroll
            for (int mt=0; mt<4; mt++)
#pragma unroll
                for (int nt=0; nt<4; nt++) {
                    const uint32_t b0 = bb[nt>>1][(nt&1)*2];
                    const uint32_t b1 = bb[nt>>1][(nt&1)*2+1];
                    MMA_BF16(acc[mt][nt][0], acc[mt][nt][1],
                             acc[mt][nt][2], acc[mt][nt][3],
                             a[mt][0], a[mt][1], a[mt][2], a[mt][3], b0, b1);
                }
        }
    }

    __syncthreads();
    const int g  = lane >> 2;
    const uint32_t stLane = smBase +
        (uint32_t)(((lane & 7) * 72 + ((lane & 8) ? 8 : 0)) * 2);
#pragma unroll
    for (int mt=0; mt<4; mt++) {
        const int k0 = mt*16 + g;
        const float* bp = (mt < 2) ? f_b : g_b;
        const float bv0 = bp[k0 & 31];
        const float bv8 = bp[(k0 + 8) & 31];
#pragma unroll
        for (int nt=0; nt<4; nt++) {
            __nv_bfloat162 q0 = __float22bfloat162_rn(
                make_float2(acc[mt][nt][0] + bv0, acc[mt][nt][1] + bv0));
            __nv_bfloat162 q1 = __float22bfloat162_rn(
                make_float2(acc[mt][nt][2] + bv8, acc[mt][nt][3] + bv8));
            const uint32_t addr = stLane +
                (uint32_t)(((warpN*32 + nt*8)*72 + mt*16) * 2);
            STSM_X2_TRANS(addr,
                          reinterpret_cast<uint32_t&>(q0),
                          reinterpret_cast<uint32_t&>(q1));
        }
    }
    __syncthreads();

    {
        const char* row = smf + (size_t)tid * 144;
        uint4* fDst = reinterpret_cast<uint4*>(&g_fT[z][nBase + tid][0]);
        uint4* gDst = reinterpret_cast<uint4*>(&g_gT[z][nBase + tid][0]);
#pragma unroll
        for (int j=0;j<4;j++)
            fDst[j] = *reinterpret_cast<const uint4*>(row + j*16);
#pragma unroll
        for (int j=0;j<4;j++)
            gDst[j] = *reinterpret_cast<const uint4*>(row + 64 + j*16);
    }
}

// =====================================================================
// Kernel 2 (fused, single pass, dynamic tiles): scores + exp + stmatrix
// staging + Pt write + invsum.  512 tiles.  (frozen)
// =====================================================================
#define FLD   40
#define FSM_FT   0u
#define FSM_G    5120u
#define FSM_GSZ  20480u
#define FSM_ST   46080u
#define FSM_RED  82944u
#define FSM_TOTAL 83968u
#define SM_TILES 512

__global__ __launch_bounds__(256) void fused_sm_kernel()
{
    extern __shared__ __align__(16) char sm[];
    __shared__ unsigned int s_tile;
    const uint32_t smBase = smem_u32(sm);
    float* red = reinterpret_cast<float*>(sm + FSM_RED);

    const int tid  = threadIdx.x;
    const int lane = tid & 31, wid = tid >> 5;
    const int warpM = wid >> 2;
    const int warpN = wid & 3;
    const int qg = lane >> 2, tq = lane & 3;

    const int lm  = lane & 15;
    const int aco = (lane >= 16) ? 8 : 0;
    uint32_t aAddr[2];
#pragma unroll
    for (int mt=0; mt<2; mt++)
        aAddr[mt] = smBase + FSM_FT +
            (uint32_t)(((warpM*32 + mt*16 + lm)*FLD + aco)*2);
    const int bro = (lane & 7) + ((lane >= 16) ? 8 : 0);
    const int bco = (lane & 8) ? 8 : 0;
    uint32_t bOff[4];
#pragma unroll
    for (int p=0; p<4; p++)
        bOff[p] = (uint32_t)(((warpN*64 + p*16 + bro)*FLD + bco)*2);

    const int grow = tid >> 2, gch = tid & 3;
    const uint32_t stLane = smBase + FSM_ST +
        (uint32_t)(((lane & 7) * 72 + ((lane & 8) ? 8 : 0)) * 2);

    const float CEXP  = 0.17677669529663688f * 1.4426950408889634f;
    const float SHIFT = 16.0f * 1.4426950408889634f;

    for (;;) {
        if (tid == 0) s_tile = atomicAdd(&g_ctr_sm, 1u);
        __syncthreads();
        const unsigned int tile = s_tile;
        if (tile >= SM_TILES) return;
        const int z  = (int)(tile >> 6);
        const int n0 = (int)(tile & 63) * 64;

        {
            const int row = tid >> 2, ch = tid & 3;
            CP_ASYNC16(smBase + FSM_FT + (uint32_t)((row*FLD + ch*8)*2),
                       (const char*)&g_fT[z][n0 + row][ch*8]);
        }
        CP_ASYNC_COMMIT();

        float rsum[4];
#pragma unroll
        for (int i=0;i<4;i++) rsum[i] = 0.f;

        {
            const char* src = (const char*)&g_gT[z][0][0];
#pragma unroll
            for (int i=0;i<4;i++)
                CP_ASYNC16(smBase + FSM_G + (uint32_t)(((grow+i*64)*FLD + gch*8)*2),
                           src + (size_t)(grow + i*64)*64 + gch*16);
            CP_ASYNC_COMMIT();
        }
        for (int t = 0; t < 16; ++t) {
            if (t < 15) {
                const uint32_t dst = smBase + FSM_G + (uint32_t)((t+1)&1)*FSM_GSZ;
                const char* src = (const char*)&g_gT[z][(t+1)*256][0];
#pragma unroll
                for (int i=0;i<4;i++)
                    CP_ASYNC16(dst + (uint32_t)(((grow+i*64)*FLD + gch*8)*2),
                               src + (size_t)(grow + i*64)*64 + gch*16);
                CP_ASYNC_COMMIT();
                CP_ASYNC_WAIT_1();
            } else {
                CP_ASYNC_WAIT_0();
            }
            __syncthreads();

            const uint32_t gb = smBase + FSM_G + (uint32_t)(t&1)*FSM_GSZ;
            float acc[2][8][4];
#pragma unroll
            for (int mt=0;mt<2;mt++)
#pragma unroll
                for (int nt=0;nt<8;nt++)
#pragma unroll
                    for (int c=0;c<4;c++) acc[mt][nt][c] = 0.f;

#pragma unroll
            for (int ks = 0; ks < 2; ++ks) {
                uint32_t a[2][4];
#pragma unroll
                for (int mt=0; mt<2; mt++)
                    LDSM_X4(a[mt][0], a[mt][1], a[mt][2], a[mt][3],
                            aAddr[mt] + ks*32);
                uint32_t bb[4][4];
#pragma unroll
                for (int p=0; p<4; p++)
                    LDSM_X4(bb[p][0], bb[p][1], bb[p][2], bb[p][3],
                            gb + bOff[p] + ks*32);
#pragma unroll
                for (int mt=0; mt<2; mt++)
#pragma unroll
                    for (int nt=0; nt<8; nt++) {
                        const uint32_t b0 = bb[nt>>1][(nt&1)*2];
                        const uint32_t b1 = bb[nt>>1][(nt&1)*2+1];
                        MMA_BF16(acc[mt][nt][0], acc[mt][nt][1],
                                 acc[mt][nt][2], acc[mt][nt][3],
                                 a[mt][0], a[mt][1], a[mt][2], a[mt][3], b0, b1);
                    }
            }

            {
#pragma unroll
                for (int mt=0;mt<2;mt++)
#pragma unroll
                    for (int nt=0;nt<8;nt++){
                        const float p0 = ex2f(fmaf(acc[mt][nt][0], CEXP, -SHIFT));
                        const float p1 = ex2f(fmaf(acc[mt][nt][1], CEXP, -SHIFT));
                        const float p2 = ex2f(fmaf(acc[mt][nt][2], CEXP, -SHIFT));
                        const float p3 = ex2f(fmaf(acc[mt][nt][3], CEXP, -SHIFT));
                        rsum[mt*2+0] += p0 + p1;
                        rsum[mt*2+1] += p2 + p3;
                        __nv_bfloat162 q0 = __float22bfloat162_rn(make_float2(p0, p1));
                        __nv_bfloat162 q1 = __float22bfloat162_rn(make_float2(p2, p3));
                        const uint32_t addr = stLane +
                            (uint32_t)(((warpN*64 + nt*8)*72 + warpM*32 + mt*16) * 2);
                        STSM_X2_TRANS(addr,
                                      reinterpret_cast<uint32_t&>(q0),
                                      reinterpret_cast<uint32_t&>(q1));
                    }
                __syncthreads();
                const int ch = tid & 7;
#pragma unroll
                for (int i=0;i<8;i++){
                    const int ml = (tid>>3) + i*32;
                    const uint4 v = *reinterpret_cast<const uint4*>(
                        sm + FSM_ST + (uint32_t)((ml*72 + ch*8)*2));
                    *reinterpret_cast<uint4*>(&g_Pt[z][t*256 + ml][n0 + ch*8]) = v;
                }
                __syncthreads();
            }
        }

#pragma unroll
        for (int i=0;i<4;i++){
            float v = rsum[i];
            v += __shfl_xor_sync(0xffffffffu, v, 1);
            v += __shfl_xor_sync(0xffffffffu, v, 2);
            rsum[i] = v;
        }
        if (tq == 0) {
#pragma unroll
            for (int i=0;i<4;i++){
                const int r = warpM*32 + (i>>1)*16 + qg + (i&1)*8;
                red[r*4 + warpN] = rsum[i];
            }
        }
        __syncthreads();
        if (warpN == 0 && tq == 0) {
#pragma unroll
            for (int i=0;i<4;i++){
                const int r = warpM*32 + (i>>1)*16 + qg + (i&1)*8;
                const float s = red[r*4+0] + red[r*4+1] + red[r*4+2] + red[r*4+3];
                g_invsum[z][n0 + r] = 1.0f / s;
            }
        }
    }
}

// =====================================================================
// Kernel 3 (dynamic tiles + cross-tile prefetch): h projection via HMMA.
// 1024 tiles.  Next tile's cp.async loads are issued during the current
// tile's stage-1 compute and epilogue.
// =====================================================================
#define PH_LDA   136
#define PH_AST   (64*PH_LDA*2)
#define PH_BST   (128*PH_LDA*2)
#define PH_STG   (PH_AST + PH_BST)
#define PH_SMEM  (2*PH_STG)
#define PH_TILES 1024

__global__ void __launch_bounds__(128, 2) proj_h_mma_kernel(
    const float* __restrict__ h1b, const float* __restrict__ h2b)
{
    extern __shared__ char smh[];
    __shared__ unsigned int s_tile;
    const uint32_t smBase = smem_u32(smh);

    const int tid = threadIdx.x;
    const int wid = tid >> 5, lane = tid & 31;

    const int warpN = wid;
    const int lm  = lane & 15;
    const int aco = (lane >= 16) ? 8 : 0;
    uint32_t aOff[4];
#pragma unroll
    for (int mt=0; mt<4; mt++)
        aOff[mt] = (uint32_t)(((mt*16 + lm)*PH_LDA + aco)*2);
    const int bro = (lane & 7) + ((lane >= 16) ? 8 : 0);
    const int bco = (lane & 8) ? 8 : 0;
    uint32_t bOffA[2];
#pragma unroll
    for (int p=0; p<2; p++)
        bOffA[p] = PH_AST + (uint32_t)(((warpN*32 + p*16 + bro)*PH_LDA + bco)*2);

    const int arow = tid >> 1;
    const int ahalf = (tid & 1) * 128;
    const uint32_t dA = (uint32_t)(arow * (PH_LDA*2) + ahalf);
    const uint32_t dB = PH_AST + (uint32_t)(tid * (PH_LDA*2));

    // grab first tile + issue its loads
    if (tid == 0) s_tile = atomicAdd(&g_ctr_ph, 1u);
    __syncthreads();
    unsigned int tile = s_tile;
    if (tile < PH_TILES) {
        const int z     = (int)(tile >> 7);
        const int oBase = (int)((tile >> 5) & 3) * 64;
        const int nBase = (int)(tile & 31) * 128;
        const int br = z >> 2;
        const char* gA = (const char*)&g_Wb[br][oBase + arow][0] + ahalf;
        const char* gB = (const char*)&g_Xt[z][nBase + tid][0];
#pragma unroll
        for (int st = 0; st < 2; ++st) {
            const uint32_t slot = smBase + (uint32_t)st * PH_STG;
#pragma unroll
            for (int j=0;j<8;j++)  CP_ASYNC16(slot + dA + j*16, gA + st*256 + j*16);
#pragma unroll
            for (int j=0;j<16;j++) CP_ASYNC16(slot + dB + j*16, gB + st*256 + j*16);
            CP_ASYNC_COMMIT();
        }
    }

    while (tile < PH_TILES) {
        const int z     = (int)(tile >> 7);
        const int oBase = (int)((tile >> 5) & 3) * 64;
        const int nBase = (int)(tile & 31) * 128;
        const int br = z >> 2;
        const float* bias = br ? h2b : h1b;

        float acc[4][4][4];
#pragma unroll
        for (int i=0;i<4;i++)
#pragma unroll
            for (int j=0;j<4;j++)
#pragma unroll
                for (int k=0;k<4;k++) acc[i][j][k] = 0.f;

        // ---- stage 0 compute ----
        CP_ASYNC_WAIT_1();
        __syncthreads();
        {
            const uint32_t slot = smBase;
#pragma unroll
            for (int ks = 0; ks < 8; ++ks) {
                uint32_t a[4][4];
#pragma unroll
                for (int mt=0; mt<4; mt++)
                    LDSM_X4(a[mt][0], a[mt][1], a[mt][2], a[mt][3],
                            slot + aOff[mt] + ks*32);
                uint32_t bb[2][4];
#pragma unroll
                for (int p=0; p<2; p++)
                    LDSM_X4(bb[p][0], bb[p][1], bb[p][2], bb[p][3],
                            slot + bOffA[p] + ks*32);
#pragma unroll
                for (int mt=0; mt<4; mt++)
#pragma unroll
                    for (int nt=0; nt<4; nt++) {
                        const uint32_t b0 = bb[nt>>1][(nt&1)*2];
                        const uint32_t b1 = bb[nt>>1][(nt&1)*2+1];
                        MMA_BF16(acc[mt][nt][0], acc[mt][nt][1],
                                 acc[mt][nt][2], acc[mt][nt][3],
                                 a[mt][0], a[mt][1], a[mt][2], a[mt][3], b0, b1);
                    }
            }
        }
        if (tid == 0) s_tile = atomicAdd(&g_ctr_ph, 1u);

        // ---- stage 1 ready; slot0 drained by all warps (barrier) ----
        CP_ASYNC_WAIT_0();
        __syncthreads();
        const unsigned int nxt = s_tile;
        const char* ngA = nullptr; const char* ngB = nullptr;
        if (nxt < PH_TILES) {
            const int nz     = (int)(nxt >> 7);
            const int noBase = (int)((nxt >> 5) & 3) * 64;
            const int nnBase = (int)(nxt & 31) * 128;
            ngA = (const char*)&g_Wb[nz >> 2][noBase + arow][0] + ahalf;
            ngB = (const char*)&g_Xt[nz][nnBase + tid][0];
            // prefetch next tile stage 0 into slot 0
#pragma unroll
            for (int j=0;j<8;j++)  CP_ASYNC16(smBase + dA + j*16, ngA + j*16);
#pragma unroll
            for (int j=0;j<16;j++) CP_ASYNC16(smBase + dB + j*16, ngB + j*16);
        }
        CP_ASYNC_COMMIT();

        // ---- stage 1 compute ----
        {
            const uint32_t slot = smBase + PH_STG;
#pragma unroll
            for (int ks = 0; ks < 8; ++ks) {
                uint32_t a[4][4];
#pragma unroll
                for (int mt=0; mt<4; mt++)
                    LDSM_X4(a[mt][0], a[mt][1], a[mt][2], a[mt][3],
                            slot + aOff[mt] + ks*32);
                uint32_t bb[2][4];
#pragma unroll
                for (int p=0; p<2; p++)
                    LDSM_X4(bb[p][0], bb[p][1], bb[p][2], bb[p][3],
                            slot + bOffA[p] + ks*32);
#pragma unroll
                for (int mt=0; mt<4; mt++)
#pragma unroll
                    for (int nt=0; nt<4; nt++) {
                        const uint32_t b0 = bb[nt>>1][(nt&1)*2];
                        const uint32_t b1 = bb[nt>>1][(nt&1)*2+1];
                        MMA_BF16(acc[mt][nt][0], acc[mt][nt][1],
                                 acc[mt][nt][2], acc[mt][nt][3],
                                 a[mt][0], a[mt][1], a[mt][2], a[mt][3], b0, b1);
                    }
            }
        }
        __syncthreads();   // slot1 drained by all warps
        if (nxt < PH_TILES) {
            // prefetch next tile stage 1 into slot 1
            const uint32_t slot = smBase + PH_STG;
#pragma unroll
            for (int j=0;j<8;j++)  CP_ASYNC16(slot + dA + j*16, ngA + 256 + j*16);
#pragma unroll
            for (int j=0;j<16;j++) CP_ASYNC16(slot + dB + j*16, ngB + 256 + j*16);
        }
        CP_ASYNC_COMMIT();

        // ---- epilogue (overlaps next tile's loads) ----
        const int g  = lane >> 2;
        const int tq = lane & 3;
#pragma unroll
        for (int mt=0; mt<4; mt++) {
            const int row0 = oBase + mt*16 + g;
            const float bv0 = bias[row0];
            const float bv8 = bias[row0 + 8];
#pragma unroll
            for (int nt=0; nt<4; nt++) {
                const int col = nBase + warpN*32 + nt*8 + tq*2;
                const float2 iv = *reinterpret_cast<const float2*>(&g_invsum[z][col]);
                {
                    const float v0 = (acc[mt][nt][0] + bv0) * iv.x;
                    const float v1 = (acc[mt][nt][1] + bv0) * iv.y;
                    __nv_bfloat162 pk = __float22bfloat162_rn(make_float2(v0, v1));
                    *reinterpret_cast<uint32_t*>(&g_Hb[z][row0][col]) =
                        reinterpret_cast<uint32_t&>(pk);
                }
                {
                    const float v0 = (acc[mt][nt][2] + bv8) * iv.x;
                    const float v1 = (acc[mt][nt][3] + bv8) * iv.y;
                    __nv_bfloat162 pk = __float22bfloat162_rn(make_float2(v0, v1));
                    *reinterpret_cast<uint32_t*>(&g_Hb[z][row0 + 8][col]) =
                        reinterpret_cast<uint32_t&>(pk);
                }
            }
        }

        tile = nxt;
    }
}

// =====================================================================
// Kernel 4 (dynamic tiles): out[z] = gamma*(H'@P') + x.  512 tiles.
// Tile order: c fastest (adjacent tiles share the B panel -> L2 reuse).
// =====================================================================
#define BK      64
#define LDSS    72
#define STGB    (128*LDSS*2)
#define NSTG    3
#define OUT_SMEM (NSTG*2*STGB)
#define OUT_TILES 512

__global__ void __launch_bounds__(256, 2) out_mma_kernel(
    const float* __restrict__ x1, const float* __restrict__ x2,
    const float* __restrict__ gamma1, const float* __restrict__ gamma2,
    float* __restrict__ out)
{
    extern __shared__ char smo[];
    __shared__ unsigned int s_tile;
    const uint32_t smBase = smem_u32(smo);

    const int tid = threadIdx.x;
    const int wid = tid >> 5, lane = tid & 31;

    const int lrow = tid >> 1;
    const int lcol = (tid & 1) * 32;
    const uint32_t ldOff = (uint32_t)((lrow*LDSS + lcol)*2);

    const int warpM = wid >> 2;
    const int warpN = wid & 3;
    const int lm  = lane & 15;
    const int aco = (lane >= 16) ? 8 : 0;
    uint32_t aOff[4];
#pragma unroll
    for (int mt=0; mt<4; mt++)
        aOff[mt] = (uint32_t)(((warpM*64 + mt*16 + lm)*LDSS + aco)*2);
    const int bro = (lane & 7) + ((lane >= 16) ? 8 : 0);
    const int bco = (lane & 8) ? 8 : 0;
    uint32_t bOff[2];
#pragma unroll
    for (int p=0; p<2; p++)
        bOff[p] = (uint32_t)(((warpN*32 + p*16 + bro)*LDSS + bco)*2) + STGB;

    for (;;) {
        if (tid == 0) s_tile = atomicAdd(&g_ctr_out, 1u);
        __syncthreads();
        const unsigned int tile = s_tile;
        if (tile >= OUT_TILES) return;
        // c fastest: adjacent tiles share (z, mBase) -> B panel in L2
        const int z     = (int)(tile >> 6);
        const int mBase = (int)((tile >> 1) & 31) * 128;
        const int cBase = (int)(tile & 1) * 128;
        const int br = z >> 2, b = z & 3;
        const float* X = (br ? x2 : x1) + (size_t)b * CH * NPIX;
        const float gamma = (br ? gamma2 : gamma1)[0];

        const char* gAp = (const char*)(&g_Hb[z][cBase + lrow][lcol]);
        const char* gBp = (const char*)(&g_Pt[z][mBase + lrow][lcol]);

        float acc[4][4][4];
#pragma unroll
        for (int i=0;i<4;i++)
#pragma unroll
            for (int j=0;j<4;j++)
#pragma unroll
                for (int k=0;k<4;k++) acc[i][j][k] = 0.f;

#pragma unroll
        for (int st=0; st<2; ++st) {
            const uint32_t slot = smBase + (uint32_t)st * (2*STGB);
            const char* sa = gAp + (size_t)st * (BK*2);
            const char* sb = gBp + (size_t)st * (BK*2);
#pragma unroll
            for (int j=0;j<4;j++) CP_ASYNC16(slot + ldOff + j*16, sa + j*16);
#pragma unroll
            for (int j=0;j<4;j++) CP_ASYNC16(slot + STGB + ldOff + j*16, sb + j*16);
            CP_ASYNC_COMMIT();
        }

        int slotC = 0;
        int slotP = 2;
        for (int it = 0; it < NPIX/BK; ++it) {
            CP_ASYNC_WAIT_1();
            __syncthreads();

            if (it + 2 < NPIX/BK) {
                const uint32_t slot = smBase + (uint32_t)slotP * (2*STGB);
                const char* sa = gAp + (size_t)(it+2) * (BK*2);
                const char* sb = gBp + (size_t)(it+2) * (BK*2);
#pragma unroll
                for (int j=0;j<4;j++) CP_ASYNC16(slot + ldOff + j*16, sa + j*16);
#pragma unroll
                for (int j=0;j<4;j++) CP_ASYNC16(slot + STGB + ldOff + j*16, sb + j*16);
            }
            CP_ASYNC_COMMIT();

            const uint32_t sb = smBase + (uint32_t)slotC * (2*STGB);
#pragma unroll
            for (int ks = 0; ks < 4; ++ks) {
                uint32_t a[4][4];
#pragma unroll
                for (int mt=0; mt<4; mt++)
                    LDSM_X4(a[mt][0], a[mt][1], a[mt][2], a[mt][3],
                            sb + aOff[mt] + ks*32);
                uint32_t bb[2][4];
#pragma unroll
                for (int p=0; p<2; p++)
                    LDSM_X4(bb[p][0], bb[p][1], bb[p][2], bb[p][3],
                            sb + bOff[p] + ks*32);
#pragma unroll
                for (int mt=0; mt<4; mt++)
#pragma unroll
                    for (int nt=0; nt<4; nt++) {
                        const uint32_t b0 = bb[nt>>1][(nt&1)*2];
                        const uint32_t b1 = bb[nt>>1][(nt&1)*2+1];
                        MMA_BF16(acc[mt][nt][0], acc[mt][nt][1],
                                 acc[mt][nt][2], acc[mt][nt][3],
                                 a[mt][0], a[mt][1], a[mt][2], a[mt][3], b0, b1);
                    }
            }

            slotC = (slotC == 2) ? 0 : slotC + 1;
            slotP = (slotP == 2) ? 0 : slotP + 1;
        }

        const int g  = lane >> 2;
        const int tq = lane & 3;
        float* Cz = out + (size_t)z * CH * NPIX;
#pragma unroll
        for (int mt=0; mt<4; mt++) {
            const int row = cBase + warpM*64 + mt*16 + g;
#pragma unroll
            for (int nt=0; nt<4; nt++) {
                const int col = mBase + warpN*32 + nt*8 + tq*2;
                {
                    const float2 xv = *reinterpret_cast<const float2*>(
                        &X[(size_t)row*NPIX + col]);
                    float2 o;
                    o.x = fmaf(gamma, acc[mt][nt][0], xv.x);
                    o.y = fmaf(gamma, acc[mt][nt][1], xv.y);
                    *reinterpret_cast<float2*>(&Cz[(size_t)row*NPIX + col]) = o;
                }
                {
                    const float2 xv = *reinterpret_cast<const float2*>(
                        &X[(size_t)(row+8)*NPIX + col]);
                    float2 o;
                    o.x = fmaf(gamma, acc[mt][nt][2], xv.x);
                    o.y = fmaf(gamma, acc[mt][nt][3], xv.y);
                    *reinterpret_cast<float2*>(&Cz[(size_t)(row+8)*NPIX + col]) = o;
                }
            }
        }
    }
}

// =====================================================================
extern "C" void kernel_launch(void* const* d_in, const int* in_sizes, int n_in,
                              void* d_out, int out_size)
{
    const float* x1     = (const float*)d_in[0];
    const float* x2     = (const float*)d_in[1];
    const float* f_w    = (const float*)d_in[2];
    const float* f_b    = (const float*)d_in[3];
    const float* g_w    = (const float*)d_in[4];
    const float* g_b    = (const float*)d_in[5];
    const float* h1_w   = (const float*)d_in[6];
    const float* h1_b   = (const float*)d_in[7];
    const float* h2_w   = (const float*)d_in[8];
    const float* h2_b   = (const float*)d_in[9];
    const float* gamma1 = (const float*)d_in[10];
    const float* gamma2 = (const float*)d_in[11];
    float* out = (float*)d_out;

    cudaFuncSetAttribute(proj_fg_mma_kernel,
                         cudaFuncAttributeMaxDynamicSharedMemorySize, FG_SMEM);
    cudaFuncSetAttribute(fused_sm_kernel,
                         cudaFuncAttributeMaxDynamicSharedMemorySize, FSM_TOTAL);
    cudaFuncSetAttribute(proj_h_mma_kernel,
                         cudaFuncAttributeMaxDynamicSharedMemorySize, PH_SMEM);
    cudaFuncSetAttribute(out_mma_kernel,
                         cudaFuncAttributeMaxDynamicSharedMemorySize, OUT_SMEM);

    prep_kernel       <<<XT_BLKS + WC_BLKS, 256>>>(
        x1, x2, f_w, g_w, h1_w, h2_w);
    proj_fg_mma_kernel<<<dim3(32, NZ), 128, FG_SMEM>>>(f_b, g_b);
    fused_sm_kernel   <<<dim3(64, NZ), 256, FSM_TOTAL>>>();
    proj_h_mma_kernel <<<dim3(32, 4, NZ), 128, PH_SMEM>>>(h1_b, h2_b);
    out_mma_kernel    <<<dim3(32, 2, NZ), 256, OUT_SMEM>>>(x1, x2, gamma1, gamma2, out);
}

// round 15
// speedup vs baseline: 1.0377x; 1.0377x over previous
#include <cuda_runtime.h>
#include <cuda_bf16.h>
#include <cstdint>
#include <math.h>

#define NBATCH 4
#define CH     256
#define NPIX   4096
#define KD     32
#define NZ     8   // 2 branches x 4 batches

// ---- scratch (module-load allocated; no runtime alloc) ----
__device__ __nv_bfloat16 g_fT[NZ][NPIX][KD];         // f^T : [n][k] bf16
__device__ __nv_bfloat16 g_gT[NZ][NPIX][KD];         // g^T : [m][k] bf16
__device__ float         g_invsum[NZ][NPIX];         // 1 / softmax row sum (shifted)
__device__ __nv_bfloat16 g_Xt[NZ][NPIX][CH];         // x^T : [n][c] bf16
__device__ __nv_bfloat16 g_Wb[2][CH][CH];            // h weights, bf16
__device__ __nv_bfloat16 g_Wfg[2*KD][CH];            // stacked [f_w; g_w], bf16
__device__ __nv_bfloat16 g_Hb[NZ][CH][NPIX];         // h projection (invsum-scaled), bf16
__device__ __nv_bfloat16 g_Pt[NZ][NPIX][NPIX];       // unnormalized P^T bf16: Pt[m][n]

// dynamic tile counters (reset by prep each launch)
__device__ unsigned int g_ctr_out;
__device__ unsigned int g_ctr_sm;
__device__ unsigned int g_ctr_ph;

__device__ __forceinline__ uint32_t smem_u32(const void* p) {
    uint32_t a;
    asm("{ .reg .u64 t; cvta.to.shared.u64 t, %1; cvt.u32.u64 %0, t; }" : "=r"(a) : "l"(p));
    return a;
}

__device__ __forceinline__ float ex2f(float x) {
    float r;
    asm("ex2.approx.f32 %0, %1;" : "=f"(r) : "f"(x));
    return r;
}

#define CP_ASYNC16(dst, src) \
    asm volatile("cp.async.cg.shared.global [%0], [%1], 16;" :: "r"(dst), "l"(src))
#define CP_ASYNC_COMMIT() asm volatile("cp.async.commit_group;" ::: "memory")
#define CP_ASYNC_WAIT_1() asm volatile("cp.async.wait_group 1;" ::: "memory")
#define CP_ASYNC_WAIT_0() asm volatile("cp.async.wait_group 0;" ::: "memory")

#define LDSM_X4(r0,r1,r2,r3,addr) \
    asm volatile("ldmatrix.sync.aligned.m8n8.x4.shared.b16 {%0,%1,%2,%3}, [%4];" \
        : "=r"(r0), "=r"(r1), "=r"(r2), "=r"(r3) : "r"(addr))

#define STSM_X2_TRANS(addr, r0, r1) \
    asm volatile("stmatrix.sync.aligned.m8n8.x2.trans.shared.b16 [%0], {%1, %2};" \
        :: "r"(addr), "r"(r0), "r"(r1) : "memory")

#define MMA_BF16(c0,c1,c2,c3,a0,a1,a2,a3,b0,b1) \
    asm volatile("mma.sync.aligned.m16n8k16.row.col.f32.bf16.bf16.f32 " \
        "{%0,%1,%2,%3}, {%4,%5,%6,%7}, {%8,%9}, {%0,%1,%2,%3};" \
        : "+f"(c0), "+f"(c1), "+f"(c2), "+f"(c3) \
        : "r"(a0), "r"(a1), "r"(a2), "r"(a3), "r"(b0), "r"(b1))

// =====================================================================
// Kernel P (merged prep): xt transpose (2048 blocks) + weight convert
// (32 blocks) + counter reset.
// =====================================================================
#define XT_BLKS 2048
#define WC_BLKS 32

__global__ __launch_bounds__(256) void prep_kernel(
    const float* __restrict__ x1, const float* __restrict__ x2,
    const float* __restrict__ f_w, const float* __restrict__ g_w,
    const float* __restrict__ h1w, const float* __restrict__ h2w)
{
    const int bx = blockIdx.x;
    const int tid = threadIdx.x;

    if (bx < XT_BLKS) {
        const int z  = bx >> 8;
        const int ct = (bx >> 6) & 3;
        const int nt = bx & 63;
        const int br = z >> 2, b = z & 3;
        const float* X = (br ? x2 : x1) + (size_t)b * CH * NPIX;
        const int n0 = nt * 64;
        const int c0 = ct * 64;

        __shared__ unsigned short t[64][66];
        const int rr = tid >> 4;
        const int c4 = (tid & 15) * 4;

#pragma unroll
        for (int p=0;p<4;p++){
            const int crow = rr + p*16;
            const float4 v = *reinterpret_cast<const float4*>(
                &X[(size_t)(c0 + crow) * NPIX + n0 + c4]);
            t[crow][c4+0] = __bfloat16_as_ushort(__float2bfloat16(v.x));
            t[crow][c4+1] = __bfloat16_as_ushort(__float2bfloat16(v.y));
            t[crow][c4+2] = __bfloat16_as_ushort(__float2bfloat16(v.z));
            t[crow][c4+3] = __bfloat16_as_ushort(__float2bfloat16(v.w));
        }
        __syncthreads();

#pragma unroll
        for (int p=0;p<4;p++){
            const int nrow = rr + p*16;
            uint2 u;
            u.x = (uint32_t)t[c4+0][nrow] | ((uint32_t)t[c4+1][nrow] << 16);
            u.y = (uint32_t)t[c4+2][nrow] | ((uint32_t)t[c4+3][nrow] << 16);
            *reinterpret_cast<uint2*>(&g_Xt[z][n0 + nrow][c0 + c4]) = u;
        }
    } else {
        const int blk = bx - XT_BLKS;
        if (blk == 0 && tid == 0) {
            g_ctr_out = 0; g_ctr_sm = 0; g_ctr_ph = 0;
        }
        const int idx = (blk * 256 + tid) * 8;
#pragma unroll
        for (int w = 0; w < 2; ++w) {
            const float* src = (w ? h2w : h1w) + idx;
            __nv_bfloat16* dst = &g_Wb[w][0][0] + idx;
#pragma unroll
            for (int j = 0; j < 2; ++j) {
                const float4 v = *reinterpret_cast<const float4*>(src + j*4);
                __nv_bfloat162 p0 = __float22bfloat162_rn(make_float2(v.x, v.y));
                __nv_bfloat162 p1 = __float22bfloat162_rn(make_float2(v.z, v.w));
                uint2 u;
                u.x = reinterpret_cast<uint32_t&>(p0);
                u.y = reinterpret_cast<uint32_t&>(p1);
                *reinterpret_cast<uint2*>(dst + j*4) = u;
            }
        }
        const int fgIdx = blk * 256 + tid;   // 0..8191
        if (fgIdx < KD * CH) {
            (&g_Wfg[0][0])[fgIdx]  = __float2bfloat16(f_w[fgIdx]);
            (&g_Wfg[KD][0])[fgIdx] = __float2bfloat16(g_w[fgIdx]);
        }
    }
}

// =====================================================================
// Kernel 1: fused f/g projection via HMMA from g_Xt.  (frozen)
// =====================================================================
#define FG_LDA   136
#define FG_AST   (64*FG_LDA*2)
#define FG_BST   (128*FG_LDA*2)
#define FG_STG   (FG_AST + FG_BST)
#define FG_SMEM  (2*FG_STG)

__global__ void __launch_bounds__(128, 2) proj_fg_mma_kernel(
    const float* __restrict__ f_b, const float* __restrict__ g_b)
{
    extern __shared__ char smf[];
    const uint32_t smBase = smem_u32(smf);

    const int tid = threadIdx.x;
    const int wid = tid >> 5, lane = tid & 31;
    const int z = blockIdx.y;
    const int nBase = blockIdx.x * 128;

    const int arow = tid >> 1;
    const int ahalf = (tid & 1) * 128;
    const char* gA = (const char*)&g_Wfg[arow][0] + ahalf;
    const uint32_t dA = (uint32_t)(arow * (FG_LDA*2) + ahalf);
    const char* gB = (const char*)&g_Xt[z][nBase + tid][0];
    const uint32_t dB = FG_AST + (uint32_t)(tid * (FG_LDA*2));

#pragma unroll
    for (int st = 0; st < 2; ++st) {
        const uint32_t slot = smBase + (uint32_t)st * FG_STG;
        const char* sa = gA + (size_t)st * 256;
        const char* sb = gB + (size_t)st * 256;
#pragma unroll
        for (int j=0;j<8;j++)  CP_ASYNC16(slot + dA + j*16, sa + j*16);
#pragma unroll
        for (int j=0;j<16;j++) CP_ASYNC16(slot + dB + j*16, sb + j*16);
        CP_ASYNC_COMMIT();
    }

    const int warpN = wid;
    const int lm  = lane & 15;
    const int aco = (lane >= 16) ? 8 : 0;
    uint32_t aOff[4];
#pragma unroll
    for (int mt=0; mt<4; mt++)
        aOff[mt] = (uint32_t)(((mt*16 + lm)*FG_LDA + aco)*2);
    const int bro = (lane & 7) + ((lane >= 16) ? 8 : 0);
    const int bco = (lane & 8) ? 8 : 0;
    uint32_t bOffA[2];
#pragma unroll
    for (int p=0; p<2; p++)
        bOffA[p] = FG_AST + (uint32_t)(((warpN*32 + p*16 + bro)*FG_LDA + bco)*2);

    float acc[4][4][4];
#pragma unroll
    for (int i=0;i<4;i++)
#pragma unroll
        for (int j=0;j<4;j++)
#pragma unroll
            for (int k=0;k<4;k++) acc[i][j][k] = 0.f;

#pragma unroll
    for (int st = 0; st < 2; ++st) {
        if (st == 0) CP_ASYNC_WAIT_1(); else CP_ASYNC_WAIT_0();
        __syncthreads();
        const uint32_t slot = smBase + (uint32_t)st * FG_STG;
#pragma unroll
        for (int ks = 0; ks < 8; ++ks) {
            uint32_t a[4][4];
#pragma unroll
            for (int mt=0; mt<4; mt++)
                LDSM_X4(a[mt][0], a[mt][1], a[mt][2], a[mt][3],
                        slot + aOff[mt] + ks*32);
            uint32_t bb[2][4];
#pragma unroll
            for (int p=0; p<2; p++)
                LDSM_X4(bb[p][0], bb[p][1], bb[p][2], bb[p][3],
                        slot + bOffA[p] + ks*32);
#pragma unroll
            for (int mt=0; mt<4; mt++)
#pragma unroll
                for (int nt=0; nt<4; nt++) {
                    const uint32_t b0 = bb[nt>>1][(nt&1)*2];
                    const uint32_t b1 = bb[nt>>1][(nt&1)*2+1];
                    MMA_BF16(acc[mt][nt][0], acc[mt][nt][1],
                             acc[mt][nt][2], acc[mt][nt][3],
                             a[mt][0], a[mt][1], a[mt][2], a[mt][3], b0, b1);
                }
        }
    }

    __syncthreads();
    const int g  = lane >> 2;
    const uint32_t stLane = smBase +
        (uint32_t)(((lane & 7) * 72 + ((lane & 8) ? 8 : 0)) * 2);
#pragma unroll
    for (int mt=0; mt<4; mt++) {
        const int k0 = mt*16 + g;
        const float* bp = (mt < 2) ? f_b : g_b;
        const float bv0 = bp[k0 & 31];
        const float bv8 = bp[(k0 + 8) & 31];
#pragma unroll
        for (int nt=0; nt<4; nt++) {
            __nv_bfloat162 q0 = __float22bfloat162_rn(
                make_float2(acc[mt][nt][0] + bv0, acc[mt][nt][1] + bv0));
            __nv_bfloat162 q1 = __float22bfloat162_rn(
                make_float2(acc[mt][nt][2] + bv8, acc[mt][nt][3] + bv8));
            const uint32_t addr = stLane +
                (uint32_t)(((warpN*32 + nt*8)*72 + mt*16) * 2);
            STSM_X2_TRANS(addr,
                          reinterpret_cast<uint32_t&>(q0),
                          reinterpret_cast<uint32_t&>(q1));
        }
    }
    __syncthreads();

    {
        const char* row = smf + (size_t)tid * 144;
        uint4* fDst = reinterpret_cast<uint4*>(&g_fT[z][nBase + tid][0]);
        uint4* gDst = reinterpret_cast<uint4*>(&g_gT[z][nBase + tid][0]);
#pragma unroll
        for (int j=0;j<4;j++)
            fDst[j] = *reinterpret_cast<const uint4*>(row + j*16);
#pragma unroll
        for (int j=0;j<4;j++)
            gDst[j] = *reinterpret_cast<const uint4*>(row + 64 + j*16);
    }
}

// =====================================================================
// Kernel 2 (fused, single pass, dynamic tiles): scores + exp + stmatrix
// staging + Pt write + invsum.  512 tiles.
// NEW: Pt STG of iteration t-1 hoisted into iteration t's MMA window;
// 2 syncs/iter instead of 3.  Bit-identical output.
// =====================================================================
#define FLD   40
#define FSM_FT   0u
#define FSM_G    5120u
#define FSM_GSZ  20480u
#define FSM_ST   46080u
#define FSM_RED  82944u
#define FSM_TOTAL 83968u
#define SM_TILES 512

__global__ __launch_bounds__(256) void fused_sm_kernel()
{
    extern __shared__ __align__(16) char sm[];
    __shared__ unsigned int s_tile;
    const uint32_t smBase = smem_u32(sm);
    float* red = reinterpret_cast<float*>(sm + FSM_RED);

    const int tid  = threadIdx.x;
    const int lane = tid & 31, wid = tid >> 5;
    const int warpM = wid >> 2;
    const int warpN = wid & 3;
    const int qg = lane >> 2, tq = lane & 3;

    const int lm  = lane & 15;
    const int aco = (lane >= 16) ? 8 : 0;
    uint32_t aAddr[2];
#pragma unroll
    for (int mt=0; mt<2; mt++)
        aAddr[mt] = smBase + FSM_FT +
            (uint32_t)(((warpM*32 + mt*16 + lm)*FLD + aco)*2);
    const int bro = (lane & 7) + ((lane >= 16) ? 8 : 0);
    const int bco = (lane & 8) ? 8 : 0;
    uint32_t bOff[4];
#pragma unroll
    for (int p=0; p<4; p++)
        bOff[p] = (uint32_t)(((warpN*64 + p*16 + bro)*FLD + bco)*2);

    const int grow = tid >> 2, gch = tid & 3;
    const uint32_t stLane = smBase + FSM_ST +
        (uint32_t)(((lane & 7) * 72 + ((lane & 8) ? 8 : 0)) * 2);

    const float CEXP  = 0.17677669529663688f * 1.4426950408889634f;
    const float SHIFT = 16.0f * 1.4426950408889634f;

    for (;;) {
        if (tid == 0) s_tile = atomicAdd(&g_ctr_sm, 1u);
        __syncthreads();
        const unsigned int tile = s_tile;
        if (tile >= SM_TILES) return;
        const int z  = (int)(tile >> 6);
        const int n0 = (int)(tile & 63) * 64;

        {
            const int row = tid >> 2, ch = tid & 3;
            CP_ASYNC16(smBase + FSM_FT + (uint32_t)((row*FLD + ch*8)*2),
                       (const char*)&g_fT[z][n0 + row][ch*8]);
        }
        CP_ASYNC_COMMIT();

        float rsum[4];
#pragma unroll
        for (int i=0;i<4;i++) rsum[i] = 0.f;

        {
            const char* src = (const char*)&g_gT[z][0][0];
#pragma unroll
            for (int i=0;i<4;i++)
                CP_ASYNC16(smBase + FSM_G + (uint32_t)(((grow+i*64)*FLD + gch*8)*2),
                           src + (size_t)(grow + i*64)*64 + gch*16);
            CP_ASYNC_COMMIT();
        }
        for (int t = 0; t < 16; ++t) {
            if (t < 15) {
                const uint32_t dst = smBase + FSM_G + (uint32_t)((t+1)&1)*FSM_GSZ;
                const char* src = (const char*)&g_gT[z][(t+1)*256][0];
#pragma unroll
                for (int i=0;i<4;i++)
                    CP_ASYNC16(dst + (uint32_t)(((grow+i*64)*FLD + gch*8)*2),
                               src + (size_t)(grow + i*64)*64 + gch*16);
                CP_ASYNC_COMMIT();
                CP_ASYNC_WAIT_1();
            } else {
                CP_ASYNC_WAIT_0();
            }
            __syncthreads();   // g(t) ready; STSM(t-1) visible to all warps

            // ---- drain staging of tile t-1 to global (overlaps MMA) ----
            if (t > 0) {
                const int ch = tid & 7;
#pragma unroll
                for (int i=0;i<8;i++){
                    const int ml = (tid>>3) + i*32;
                    const uint4 v = *reinterpret_cast<const uint4*>(
                        sm + FSM_ST + (uint32_t)((ml*72 + ch*8)*2));
                    *reinterpret_cast<uint4*>(&g_Pt[z][(t-1)*256 + ml][n0 + ch*8]) = v;
                }
            }

            const uint32_t gb = smBase + FSM_G + (uint32_t)(t&1)*FSM_GSZ;
            float acc[2][8][4];
#pragma unroll
            for (int mt=0;mt<2;mt++)
#pragma unroll
                for (int nt=0;nt<8;nt++)
#pragma unroll
                    for (int c=0;c<4;c++) acc[mt][nt][c] = 0.f;

#pragma unroll
            for (int ks = 0; ks < 2; ++ks) {
                uint32_t a[2][4];
#pragma unroll
                for (int mt=0; mt<2; mt++)
                    LDSM_X4(a[mt][0], a[mt][1], a[mt][2], a[mt][3],
                            aAddr[mt] + ks*32);
                uint32_t bb[4][4];
#pragma unroll
                for (int p=0; p<4; p++)
                    LDSM_X4(bb[p][0], bb[p][1], bb[p][2], bb[p][3],
                            gb + bOff[p] + ks*32);
#pragma unroll
                for (int mt=0; mt<2; mt++)
#pragma unroll
                    for (int nt=0; nt<8; nt++) {
                        const uint32_t b0 = bb[nt>>1][(nt&1)*2];
                        const uint32_t b1 = bb[nt>>1][(nt&1)*2+1];
                        MMA_BF16(acc[mt][nt][0], acc[mt][nt][1],
                                 acc[mt][nt][2], acc[mt][nt][3],
                                 a[mt][0], a[mt][1], a[mt][2], a[mt][3], b0, b1);
                    }
            }

            __syncthreads();   // all warps done reading staging(t-1)

            // ---- exp + rsum + stmatrix staging of tile t ----
#pragma unroll
            for (int mt=0;mt<2;mt++)
#pragma unroll
                for (int nt=0;nt<8;nt++){
                    const float p0 = ex2f(fmaf(acc[mt][nt][0], CEXP, -SHIFT));
                    const float p1 = ex2f(fmaf(acc[mt][nt][1], CEXP, -SHIFT));
                    const float p2 = ex2f(fmaf(acc[mt][nt][2], CEXP, -SHIFT));
                    const float p3 = ex2f(fmaf(acc[mt][nt][3], CEXP, -SHIFT));
                    rsum[mt*2+0] += p0 + p1;
                    rsum[mt*2+1] += p2 + p3;
                    __nv_bfloat162 q0 = __float22bfloat162_rn(make_float2(p0, p1));
                    __nv_bfloat162 q1 = __float22bfloat162_rn(make_float2(p2, p3));
                    const uint32_t addr = stLane +
                        (uint32_t)(((warpN*64 + nt*8)*72 + warpM*32 + mt*16) * 2);
                    STSM_X2_TRANS(addr,
                                  reinterpret_cast<uint32_t&>(q0),
                                  reinterpret_cast<uint32_t&>(q1));
                }
        }

        // ---- final staging drain (tile t=15) ----
        __syncthreads();
        {
            const int ch = tid & 7;
#pragma unroll
            for (int i=0;i<8;i++){
                const int ml = (tid>>3) + i*32;
                const uint4 v = *reinterpret_cast<const uint4*>(
                    sm + FSM_ST + (uint32_t)((ml*72 + ch*8)*2));
                *reinterpret_cast<uint4*>(&g_Pt[z][15*256 + ml][n0 + ch*8]) = v;
            }
        }

        // ---- reduce rsum, write invsum ----
#pragma unroll
        for (int i=0;i<4;i++){
            float v = rsum[i];
            v += __shfl_xor_sync(0xffffffffu, v, 1);
            v += __shfl_xor_sync(0xffffffffu, v, 2);
            rsum[i] = v;
        }
        if (tq == 0) {
#pragma unroll
            for (int i=0;i<4;i++){
                const int r = warpM*32 + (i>>1)*16 + qg + (i&1)*8;
                red[r*4 + warpN] = rsum[i];
            }
        }
        __syncthreads();
        if (warpN == 0 && tq == 0) {
#pragma unroll
            for (int i=0;i<4;i++){
                const int r = warpM*32 + (i>>1)*16 + qg + (i&1)*8;
                const float s = red[r*4+0] + red[r*4+1] + red[r*4+2] + red[r*4+3];
                g_invsum[z][n0 + r] = 1.0f / s;
            }
        }
        __syncthreads();   // red reuse across tiles
    }
}

// =====================================================================
// Kernel 3 (dynamic tiles + cross-tile prefetch): h projection via HMMA.
// 1024 tiles.  (unchanged from round 14)
// =====================================================================
#define PH_LDA   136
#define PH_AST   (64*PH_LDA*2)
#define PH_BST   (128*PH_LDA*2)
#define PH_STG   (PH_AST + PH_BST)
#define PH_SMEM  (2*PH_STG)
#define PH_TILES 1024

__global__ void __launch_bounds__(128, 2) proj_h_mma_kernel(
    const float* __restrict__ h1b, const float* __restrict__ h2b)
{
    extern __shared__ char smh[];
    __shared__ unsigned int s_tile;
    const uint32_t smBase = smem_u32(smh);

    const int tid = threadIdx.x;
    const int wid = tid >> 5, lane = tid & 31;

    const int warpN = wid;
    const int lm  = lane & 15;
    const int aco = (lane >= 16) ? 8 : 0;
    uint32_t aOff[4];
#pragma unroll
    for (int mt=0; mt<4; mt++)
        aOff[mt] = (uint32_t)(((mt*16 + lm)*PH_LDA + aco)*2);
    const int bro = (lane & 7) + ((lane >= 16) ? 8 : 0);
    const int bco = (lane & 8) ? 8 : 0;
    uint32_t bOffA[2];
#pragma unroll
    for (int p=0; p<2; p++)
        bOffA[p] = PH_AST + (uint32_t)(((warpN*32 + p*16 + bro)*PH_LDA + bco)*2);

    const int arow = tid >> 1;
    const int ahalf = (tid & 1) * 128;
    const uint32_t dA = (uint32_t)(arow * (PH_LDA*2) + ahalf);
    const uint32_t dB = PH_AST + (uint32_t)(tid * (PH_LDA*2));

    if (tid == 0) s_tile = atomicAdd(&g_ctr_ph, 1u);
    __syncthreads();
    unsigned int tile = s_tile;
    if (tile < PH_TILES) {
        const int z     = (int)(tile >> 7);
        const int oBase = (int)((tile >> 5) & 3) * 64;
        const int nBase = (int)(tile & 31) * 128;
        const int br = z >> 2;
        const char* gA = (const char*)&g_Wb[br][oBase + arow][0] + ahalf;
        const char* gB = (const char*)&g_Xt[z][nBase + tid][0];
#pragma unroll
        for (int st = 0; st < 2; ++st) {
            const uint32_t slot = smBase + (uint32_t)st * PH_STG;
#pragma unroll
            for (int j=0;j<8;j++)  CP_ASYNC16(slot + dA + j*16, gA + st*256 + j*16);
#pragma unroll
            for (int j=0;j<16;j++) CP_ASYNC16(slot + dB + j*16, gB + st*256 + j*16);
            CP_ASYNC_COMMIT();
        }
    }

    while (tile < PH_TILES) {
        const int z     = (int)(tile >> 7);
        const int oBase = (int)((tile >> 5) & 3) * 64;
        const int nBase = (int)(tile & 31) * 128;
        const int br = z >> 2;
        const float* bias = br ? h2b : h1b;

        float acc[4][4][4];
#pragma unroll
        for (int i=0;i<4;i++)
#pragma unroll
            for (int j=0;j<4;j++)
#pragma unroll
                for (int k=0;k<4;k++) acc[i][j][k] = 0.f;

        CP_ASYNC_WAIT_1();
        __syncthreads();
        {
            const uint32_t slot = smBase;
#pragma unroll
            for (int ks = 0; ks < 8; ++ks) {
                uint32_t a[4][4];
#pragma unroll
                for (int mt=0; mt<4; mt++)
                    LDSM_X4(a[mt][0], a[mt][1], a[mt][2], a[mt][3],
                            slot + aOff[mt] + ks*32);
                uint32_t bb[2][4];
#pragma unroll
                for (int p=0; p<2; p++)
                    LDSM_X4(bb[p][0], bb[p][1], bb[p][2], bb[p][3],
                            slot + bOffA[p] + ks*32);
#pragma unroll
                for (int mt=0; mt<4; mt++)
#pragma unroll
                    for (int nt=0; nt<4; nt++) {
                        const uint32_t b0 = bb[nt>>1][(nt&1)*2];
                        const uint32_t b1 = bb[nt>>1][(nt&1)*2+1];
                        MMA_BF16(acc[mt][nt][0], acc[mt][nt][1],
                                 acc[mt][nt][2], acc[mt][nt][3],
                                 a[mt][0], a[mt][1], a[mt][2], a[mt][3], b0, b1);
                    }
            }
        }
        if (tid == 0) s_tile = atomicAdd(&g_ctr_ph, 1u);

        CP_ASYNC_WAIT_0();
        __syncthreads();
        const unsigned int nxt = s_tile;
        const char* ngA = nullptr; const char* ngB = nullptr;
        if (nxt < PH_TILES) {
            const int nz     = (int)(nxt >> 7);
            const int noBase = (int)((nxt >> 5) & 3) * 64;
            const int nnBase = (int)(nxt & 31) * 128;
            ngA = (const char*)&g_Wb[nz >> 2][noBase + arow][0] + ahalf;
            ngB = (const char*)&g_Xt[nz][nnBase + tid][0];
#pragma unroll
            for (int j=0;j<8;j++)  CP_ASYNC16(smBase + dA + j*16, ngA + j*16);
#pragma unroll
            for (int j=0;j<16;j++) CP_ASYNC16(smBase + dB + j*16, ngB + j*16);
        }
        CP_ASYNC_COMMIT();

        {
            const uint32_t slot = smBase + PH_STG;
#pragma unroll
            for (int ks = 0; ks < 8; ++ks) {
                uint32_t a[4][4];
#pragma unroll
                for (int mt=0; mt<4; mt++)
                    LDSM_X4(a[mt][0], a[mt][1], a[mt][2], a[mt][3],
                            slot + aOff[mt] + ks*32);
                uint32_t bb[2][4];
#pragma unroll
                for (int p=0; p<2; p++)
                    LDSM_X4(bb[p][0], bb[p][1], bb[p][2], bb[p][3],
                            slot + bOffA[p] + ks*32);
#pragma unroll
                for (int mt=0; mt<4; mt++)
#pragma unroll
                    for (int nt=0; nt<4; nt++) {
                        const uint32_t b0 = bb[nt>>1][(nt&1)*2];
                        const uint32_t b1 = bb[nt>>1][(nt&1)*2+1];
                        MMA_BF16(acc[mt][nt][0], acc[mt][nt][1],
                                 acc[mt][nt][2], acc[mt][nt][3],
                                 a[mt][0], a[mt][1], a[mt][2], a[mt][3], b0, b1);
                    }
            }
        }
        __syncthreads();
        if (nxt < PH_TILES) {
            const uint32_t slot = smBase + PH_STG;
#pragma unroll
            for (int j=0;j<8;j++)  CP_ASYNC16(slot + dA + j*16, ngA + 256 + j*16);
#pragma unroll
            for (int j=0;j<16;j++) CP_ASYNC16(slot + dB + j*16, ngB + 256 + j*16);
        }
        CP_ASYNC_COMMIT();

        const int g  = lane >> 2;
        const int tq = lane & 3;
#pragma unroll
        for (int mt=0; mt<4; mt++) {
            const int row0 = oBase + mt*16 + g;
            const float bv0 = bias[row0];
            const float bv8 = bias[row0 + 8];
#pragma unroll
            for (int nt=0; nt<4; nt++) {
                const int col = nBase + warpN*32 + nt*8 + tq*2;
                const float2 iv = *reinterpret_cast<const float2*>(&g_invsum[z][col]);
                {
                    const float v0 = (acc[mt][nt][0] + bv0) * iv.x;
                    const float v1 = (acc[mt][nt][1] + bv0) * iv.y;
                    __nv_bfloat162 pk = __float22bfloat162_rn(make_float2(v0, v1));
                    *reinterpret_cast<uint32_t*>(&g_Hb[z][row0][col]) =
                        reinterpret_cast<uint32_t&>(pk);
                }
                {
                    const float v0 = (acc[mt][nt][2] + bv8) * iv.x;
                    const float v1 = (acc[mt][nt][3] + bv8) * iv.y;
                    __nv_bfloat162 pk = __float22bfloat162_rn(make_float2(v0, v1));
                    *reinterpret_cast<uint32_t*>(&g_Hb[z][row0 + 8][col]) =
                        reinterpret_cast<uint32_t&>(pk);
                }
            }
        }

        tile = nxt;
    }
}

// =====================================================================
// Kernel 4 (dynamic tiles): out[z] = gamma*(H'@P') + x.  512 tiles.
// (frozen, c-fastest order)
// =====================================================================
#define BK      64
#define LDSS    72
#define STGB    (128*LDSS*2)
#define NSTG    3
#define OUT_SMEM (NSTG*2*STGB)
#define OUT_TILES 512

__global__ void __launch_bounds__(256, 2) out_mma_kernel(
    const float* __restrict__ x1, const float* __restrict__ x2,
    const float* __restrict__ gamma1, const float* __restrict__ gamma2,
    float* __restrict__ out)
{
    extern __shared__ char smo[];
    __shared__ unsigned int s_tile;
    const uint32_t smBase = smem_u32(smo);

    const int tid = threadIdx.x;
    const int wid = tid >> 5, lane = tid & 31;

    const int lrow = tid >> 1;
    const int lcol = (tid & 1) * 32;
    const uint32_t ldOff = (uint32_t)((lrow*LDSS + lcol)*2);

    const int warpM = wid >> 2;
    const int warpN = wid & 3;
    const int lm  = lane & 15;
    const int aco = (lane >= 16) ? 8 : 0;
    uint32_t aOff[4];
#pragma unroll
    for (int mt=0; mt<4; mt++)
        aOff[mt] = (uint32_t)(((warpM*64 + mt*16 + lm)*LDSS + aco)*2);
    const int bro = (lane & 7) + ((lane >= 16) ? 8 : 0);
    const int bco = (lane & 8) ? 8 : 0;
    uint32_t bOff[2];
#pragma unroll
    for (int p=0; p<2; p++)
        bOff[p] = (uint32_t)(((warpN*32 + p*16 + bro)*LDSS + bco)*2) + STGB;

    for (;;) {
        if (tid == 0) s_tile = atomicAdd(&g_ctr_out, 1u);
        __syncthreads();
        const unsigned int tile = s_tile;
        if (tile >= OUT_TILES) return;
        const int z     = (int)(tile >> 6);
        const int mBase = (int)((tile >> 1) & 31) * 128;
        const int cBase = (int)(tile & 1) * 128;
        const int br = z >> 2, b = z & 3;
        const float* X = (br ? x2 : x1) + (size_t)b * CH * NPIX;
        const float gamma = (br ? gamma2 : gamma1)[0];

        const char* gAp = (const char*)(&g_Hb[z][cBase + lrow][lcol]);
        const char* gBp = (const char*)(&g_Pt[z][mBase + lrow][lcol]);

        float acc[4][4][4];
#pragma unroll
        for (int i=0;i<4;i++)
#pragma unroll
            for (int j=0;j<4;j++)
#pragma unroll
                for (int k=0;k<4;k++) acc[i][j][k] = 0.f;

#pragma unroll
        for (int st=0; st<2; ++st) {
            const uint32_t slot = smBase + (uint32_t)st * (2*STGB);
            const char* sa = gAp + (size_t)st * (BK*2);
            const char* sb = gBp + (size_t)st * (BK*2);
#pragma unroll
            for (int j=0;j<4;j++) CP_ASYNC16(slot + ldOff + j*16, sa + j*16);
#pragma unroll
            for (int j=0;j<4;j++) CP_ASYNC16(slot + STGB + ldOff + j*16, sb + j*16);
            CP_ASYNC_COMMIT();
        }

        int slotC = 0;
        int slotP = 2;
        for (int it = 0; it < NPIX/BK; ++it) {
            CP_ASYNC_WAIT_1();
            __syncthreads();

            if (it + 2 < NPIX/BK) {
                const uint32_t slot = smBase + (uint32_t)slotP * (2*STGB);
                const char* sa = gAp + (size_t)(it+2) * (BK*2);
                const char* sb = gBp + (size_t)(it+2) * (BK*2);
#pragma unroll
                for (int j=0;j<4;j++) CP_ASYNC16(slot + ldOff + j*16, sa + j*16);
#pragma unroll
                for (int j=0;j<4;j++) CP_ASYNC16(slot + STGB + ldOff + j*16, sb + j*16);
            }
            CP_ASYNC_COMMIT();

            const uint32_t sb = smBase + (uint32_t)slotC * (2*STGB);
#pragma unroll
            for (int ks = 0; ks < 4; ++ks) {
                uint32_t a[4][4];
#pragma unroll
                for (int mt=0; mt<4; mt++)
                    LDSM_X4(a[mt][0], a[mt][1], a[mt][2], a[mt][3],
                            sb + aOff[mt] + ks*32);
                uint32_t bb[2][4];
#pragma unroll
                for (int p=0; p<2; p++)
                    LDSM_X4(bb[p][0], bb[p][1], bb[p][2], bb[p][3],
                            sb + bOff[p] + ks*32);
#pragma unroll
                for (int mt=0; mt<4; mt++)
#pragma unroll
                    for (int nt=0; nt<4; nt++) {
                        const uint32_t b0 = bb[nt>>1][(nt&1)*2];
                        const uint32_t b1 = bb[nt>>1][(nt&1)*2+1];
                        MMA_BF16(acc[mt][nt][0], acc[mt][nt][1],
                                 acc[mt][nt][2], acc[mt][nt][3],
                                 a[mt][0], a[mt][1], a[mt][2], a[mt][3], b0, b1);
                    }
            }

            slotC = (slotC == 2) ? 0 : slotC + 1;
            slotP = (slotP == 2) ? 0 : slotP + 1;
        }

        const int g  = lane >> 2;
        const int tq = lane & 3;
        float* Cz = out + (size_t)z * CH * NPIX;
#pragma unroll
        for (int mt=0; mt<4; mt++) {
            const int row = cBase + warpM*64 + mt*16 + g;
#pragma unroll
            for (int nt=0; nt<4; nt++) {
                const int col = mBase + warpN*32 + nt*8 + tq*2;
                {
                    const float2 xv = *reinterpret_cast<const float2*>(
                        &X[(size_t)row*NPIX + col]);
                    float2 o;
                    o.x = fmaf(gamma, acc[mt][nt][0], xv.x);
                    o.y = fmaf(gamma, acc[mt][nt][1], xv.y);
                    *reinterpret_cast<float2*>(&Cz[(size_t)row*NPIX + col]) = o;
                }
                {
                    const float2 xv = *reinterpret_cast<const float2*>(
                        &X[(size_t)(row+8)*NPIX + col]);
                    float2 o;
                    o.x = fmaf(gamma, acc[mt][nt][2], xv.x);
                    o.y = fmaf(gamma, acc[mt][nt][3], xv.y);
                    *reinterpret_cast<float2*>(&Cz[(size_t)(row+8)*NPIX + col]) = o;
                }
            }
        }
    }
}

// =====================================================================
extern "C" void kernel_launch(void* const* d_in, const int* in_sizes, int n_in,
                              void* d_out, int out_size)
{
    const float* x1     = (const float*)d_in[0];
    const float* x2     = (const float*)d_in[1];
    const float* f_w    = (const float*)d_in[2];
    const float* f_b    = (const float*)d_in[3];
    const float* g_w    = (const float*)d_in[4];
    const float* g_b    = (const float*)d_in[5];
    const float* h1_w   = (const float*)d_in[6];
    const float* h1_b   = (const float*)d_in[7];
    const float* h2_w   = (const float*)d_in[8];
    const float* h2_b   = (const float*)d_in[9];
    const float* gamma1 = (const float*)d_in[10];
    const float* gamma2 = (const float*)d_in[11];
    float* out = (float*)d_out;

    cudaFuncSetAttribute(proj_fg_mma_kernel,
                         cudaFuncAttributeMaxDynamicSharedMemorySize, FG_SMEM);
    cudaFuncSetAttribute(fused_sm_kernel,
                         cudaFuncAttributeMaxDynamicSharedMemorySize, FSM_TOTAL);
    cudaFuncSetAttribute(proj_h_mma_kernel,
                         cudaFuncAttributeMaxDynamicSharedMemorySize, PH_SMEM);
    cudaFuncSetAttribute(out_mma_kernel,
                         cudaFuncAttributeMaxDynamicSharedMemorySize, OUT_SMEM);

    prep_kernel       <<<XT_BLKS + WC_BLKS, 256>>>(
        x1, x2, f_w, g_w, h1_w, h2_w);
    proj_fg_mma_kernel<<<dim3(32, NZ), 128, FG_SMEM>>>(f_b, g_b);
    fused_sm_kernel   <<<dim3(64, NZ), 256, FSM_TOTAL>>>();
    proj_h_mma_kernel <<<dim3(32, 4, NZ), 128, PH_SMEM>>>(h1_b, h2_b);
    out_mma_kernel    <<<dim3(32, 2, NZ), 256, OUT_SMEM>>>(x1, x2, gamma1, gamma2, out);
}

// round 16
// speedup vs baseline: 1.0418x; 1.0039x over previous
#include <cuda_runtime.h>
#include <cuda_bf16.h>
#include <cstdint>
#include <math.h>

#define NBATCH 4
#define CH     256
#define NPIX   4096
#define KD     32
#define NZ     8   // 2 branches x 4 batches

// ---- scratch (module-load allocated; no runtime alloc) ----
__device__ __nv_bfloat16 g_fT[NZ][NPIX][KD];         // f^T : [n][k] bf16
__device__ __nv_bfloat16 g_gT[NZ][NPIX][KD];         // g^T : [m][k] bf16
__device__ float         g_invsum[NZ][NPIX];         // 1 / softmax row sum (shifted)
__device__ __nv_bfloat16 g_Xt[NZ][NPIX][CH];         // x^T : [n][c] bf16
__device__ __nv_bfloat16 g_Wb[2][CH][CH];            // h weights, bf16
__device__ __nv_bfloat16 g_Wfg[2*KD][CH];            // stacked [f_w; g_w], bf16
__device__ __nv_bfloat16 g_Hb[NZ][CH][NPIX];         // h projection (invsum-scaled), bf16
__device__ __nv_bfloat16 g_Pt[NZ][NPIX][NPIX];       // unnormalized P^T bf16: Pt[m][n]

// dynamic tile counters (reset by prep each launch)
__device__ unsigned int g_ctr_out;
__device__ unsigned int g_ctr_sm;
__device__ unsigned int g_ctr_ph;

__device__ __forceinline__ uint32_t smem_u32(const void* p) {
    uint32_t a;
    asm("{ .reg .u64 t; cvta.to.shared.u64 t, %1; cvt.u32.u64 %0, t; }" : "=r"(a) : "l"(p));
    return a;
}

__device__ __forceinline__ float ex2f(float x) {
    float r;
    asm("ex2.approx.f32 %0, %1;" : "=f"(r) : "f"(x));
    return r;
}

#define CP_ASYNC16(dst, src) \
    asm volatile("cp.async.cg.shared.global [%0], [%1], 16;" :: "r"(dst), "l"(src))
#define CP_ASYNC_COMMIT() asm volatile("cp.async.commit_group;" ::: "memory")
#define CP_ASYNC_WAIT_1() asm volatile("cp.async.wait_group 1;" ::: "memory")
#define CP_ASYNC_WAIT_0() asm volatile("cp.async.wait_group 0;" ::: "memory")

#define LDSM_X4(r0,r1,r2,r3,addr) \
    asm volatile("ldmatrix.sync.aligned.m8n8.x4.shared.b16 {%0,%1,%2,%3}, [%4];" \
        : "=r"(r0), "=r"(r1), "=r"(r2), "=r"(r3) : "r"(addr))

#define STSM_X2_TRANS(addr, r0, r1) \
    asm volatile("stmatrix.sync.aligned.m8n8.x2.trans.shared.b16 [%0], {%1, %2};" \
        :: "r"(addr), "r"(r0), "r"(r1) : "memory")

#define MMA_BF16(c0,c1,c2,c3,a0,a1,a2,a3,b0,b1) \
    asm volatile("mma.sync.aligned.m16n8k16.row.col.f32.bf16.bf16.f32 " \
        "{%0,%1,%2,%3}, {%4,%5,%6,%7}, {%8,%9}, {%0,%1,%2,%3};" \
        : "+f"(c0), "+f"(c1), "+f"(c2), "+f"(c3) \
        : "r"(a0), "r"(a1), "r"(a2), "r"(a3), "r"(b0), "r"(b1))

// =====================================================================
// Kernel P (merged prep): xt transpose (2048 blocks) + weight convert
// (32 blocks) + counter reset.
// =====================================================================
#define XT_BLKS 2048
#define WC_BLKS 32

__global__ __launch_bounds__(256) void prep_kernel(
    const float* __restrict__ x1, const float* __restrict__ x2,
    const float* __restrict__ f_w, const float* __restrict__ g_w,
    const float* __restrict__ h1w, const float* __restrict__ h2w)
{
    const int bx = blockIdx.x;
    const int tid = threadIdx.x;

    if (bx < XT_BLKS) {
        const int z  = bx >> 8;
        const int ct = (bx >> 6) & 3;
        const int nt = bx & 63;
        const int br = z >> 2, b = z & 3;
        const float* X = (br ? x2 : x1) + (size_t)b * CH * NPIX;
        const int n0 = nt * 64;
        const int c0 = ct * 64;

        __shared__ unsigned short t[64][66];
        const int rr = tid >> 4;
        const int c4 = (tid & 15) * 4;

#pragma unroll
        for (int p=0;p<4;p++){
            const int crow = rr + p*16;
            const float4 v = *reinterpret_cast<const float4*>(
                &X[(size_t)(c0 + crow) * NPIX + n0 + c4]);
            t[crow][c4+0] = __bfloat16_as_ushort(__float2bfloat16(v.x));
            t[crow][c4+1] = __bfloat16_as_ushort(__float2bfloat16(v.y));
            t[crow][c4+2] = __bfloat16_as_ushort(__float2bfloat16(v.z));
            t[crow][c4+3] = __bfloat16_as_ushort(__float2bfloat16(v.w));
        }
        __syncthreads();

#pragma unroll
        for (int p=0;p<4;p++){
            const int nrow = rr + p*16;
            uint2 u;
            u.x = (uint32_t)t[c4+0][nrow] | ((uint32_t)t[c4+1][nrow] << 16);
            u.y = (uint32_t)t[c4+2][nrow] | ((uint32_t)t[c4+3][nrow] << 16);
            *reinterpret_cast<uint2*>(&g_Xt[z][n0 + nrow][c0 + c4]) = u;
        }
    } else {
        const int blk = bx - XT_BLKS;
        if (blk == 0 && tid == 0) {
            g_ctr_out = 0; g_ctr_sm = 0; g_ctr_ph = 0;
        }
        const int idx = (blk * 256 + tid) * 8;
#pragma unroll
        for (int w = 0; w < 2; ++w) {
            const float* src = (w ? h2w : h1w) + idx;
            __nv_bfloat16* dst = &g_Wb[w][0][0] + idx;
#pragma unroll
            for (int j = 0; j < 2; ++j) {
                const float4 v = *reinterpret_cast<const float4*>(src + j*4);
                __nv_bfloat162 p0 = __float22bfloat162_rn(make_float2(v.x, v.y));
                __nv_bfloat162 p1 = __float22bfloat162_rn(make_float2(v.z, v.w));
                uint2 u;
                u.x = reinterpret_cast<uint32_t&>(p0);
                u.y = reinterpret_cast<uint32_t&>(p1);
                *reinterpret_cast<uint2*>(dst + j*4) = u;
            }
        }
        const int fgIdx = blk * 256 + tid;   // 0..8191
        if (fgIdx < KD * CH) {
            (&g_Wfg[0][0])[fgIdx]  = __float2bfloat16(f_w[fgIdx]);
            (&g_Wfg[KD][0])[fgIdx] = __float2bfloat16(g_w[fgIdx]);
        }
    }
}

// =====================================================================
// Kernel 1: fused f/g projection via HMMA from g_Xt.  (frozen)
// =====================================================================
#define FG_LDA   136
#define FG_AST   (64*FG_LDA*2)
#define FG_BST   (128*FG_LDA*2)
#define FG_STG   (FG_AST + FG_BST)
#define FG_SMEM  (2*FG_STG)

__global__ void __launch_bounds__(128, 2) proj_fg_mma_kernel(
    const float* __restrict__ f_b, const float* __restrict__ g_b)
{
    extern __shared__ char smf[];
    const uint32_t smBase = smem_u32(smf);

    const int tid = threadIdx.x;
    const int wid = tid >> 5, lane = tid & 31;
    const int z = blockIdx.y;
    const int nBase = blockIdx.x * 128;

    const int arow = tid >> 1;
    const int ahalf = (tid & 1) * 128;
    const char* gA = (const char*)&g_Wfg[arow][0] + ahalf;
    const uint32_t dA = (uint32_t)(arow * (FG_LDA*2) + ahalf);
    const char* gB = (const char*)&g_Xt[z][nBase + tid][0];
    const uint32_t dB = FG_AST + (uint32_t)(tid * (FG_LDA*2));

#pragma unroll
    for (int st = 0; st < 2; ++st) {
        const uint32_t slot = smBase + (uint32_t)st * FG_STG;
        const char* sa = gA + (size_t)st * 256;
        const char* sb = gB + (size_t)st * 256;
#pragma unroll
        for (int j=0;j<8;j++)  CP_ASYNC16(slot + dA + j*16, sa + j*16);
#pragma unroll
        for (int j=0;j<16;j++) CP_ASYNC16(slot + dB + j*16, sb + j*16);
        CP_ASYNC_COMMIT();
    }

    const int warpN = wid;
    const int lm  = lane & 15;
    const int aco = (lane >= 16) ? 8 : 0;
    uint32_t aOff[4];
#pragma unroll
    for (int mt=0; mt<4; mt++)
        aOff[mt] = (uint32_t)(((mt*16 + lm)*FG_LDA + aco)*2);
    const int bro = (lane & 7) + ((lane >= 16) ? 8 : 0);
    const int bco = (lane & 8) ? 8 : 0;
    uint32_t bOffA[2];
#pragma unroll
    for (int p=0; p<2; p++)
        bOffA[p] = FG_AST + (uint32_t)(((warpN*32 + p*16 + bro)*FG_LDA + bco)*2);

    float acc[4][4][4];
#pragma unroll
    for (int i=0;i<4;i++)
#pragma unroll
        for (int j=0;j<4;j++)
#pragma unroll
            for (int k=0;k<4;k++) acc[i][j][k] = 0.f;

#pragma unroll
    for (int st = 0; st < 2; ++st) {
        if (st == 0) CP_ASYNC_WAIT_1(); else CP_ASYNC_WAIT_0();
        __syncthreads();
        const uint32_t slot = smBase + (uint32_t)st * FG_STG;
#pragma unroll
        for (int ks = 0; ks < 8; ++ks) {
            uint32_t a[4][4];
#pragma unroll
            for (int mt=0; mt<4; mt++)
                LDSM_X4(a[mt][0], a[mt][1], a[mt][2], a[mt][3],
                        slot + aOff[mt] + ks*32);
            uint32_t bb[2][4];
#pragma unroll
            for (int p=0; p<2; p++)
                LDSM_X4(bb[p][0], bb[p][1], bb[p][2], bb[p][3],
                        slot + bOffA[p] + ks*32);
#pragma unroll
            for (int mt=0; mt<4; mt++)
#pragma unroll
                for (int nt=0; nt<4; nt++) {
                    const uint32_t b0 = bb[nt>>1][(nt&1)*2];
                    const uint32_t b1 = bb[nt>>1][(nt&1)*2+1];
                    MMA_BF16(acc[mt][nt][0], acc[mt][nt][1],
                             acc[mt][nt][2], acc[mt][nt][3],
                             a[mt][0], a[mt][1], a[mt][2], a[mt][3], b0, b1);
                }
        }
    }

    __syncthreads();
    const int g  = lane >> 2;
    const uint32_t stLane = smBase +
        (uint32_t)(((lane & 7) * 72 + ((lane & 8) ? 8 : 0)) * 2);
#pragma unroll
    for (int mt=0; mt<4; mt++) {
        const int k0 = mt*16 + g;
        const float* bp = (mt < 2) ? f_b : g_b;
        const float bv0 = bp[k0 & 31];
        const float bv8 = bp[(k0 + 8) & 31];
#pragma unroll
        for (int nt=0; nt<4; nt++) {
            __nv_bfloat162 q0 = __float22bfloat162_rn(
                make_float2(acc[mt][nt][0] + bv0, acc[mt][nt][1] + bv0));
            __nv_bfloat162 q1 = __float22bfloat162_rn(
                make_float2(acc[mt][nt][2] + bv8, acc[mt][nt][3] + bv8));
            const uint32_t addr = stLane +
                (uint32_t)(((warpN*32 + nt*8)*72 + mt*16) * 2);
            STSM_X2_TRANS(addr,
                          reinterpret_cast<uint32_t&>(q0),
                          reinterpret_cast<uint32_t&>(q1));
        }
    }
    __syncthreads();

    {
        const char* row = smf + (size_t)tid * 144;
        uint4* fDst = reinterpret_cast<uint4*>(&g_fT[z][nBase + tid][0]);
        uint4* gDst = reinterpret_cast<uint4*>(&g_gT[z][nBase + tid][0]);
#pragma unroll
        for (int j=0;j<4;j++)
            fDst[j] = *reinterpret_cast<const uint4*>(row + j*16);
#pragma unroll
        for (int j=0;j<4;j++)
            gDst[j] = *reinterpret_cast<const uint4*>(row + 64 + j*16);
    }
}

// =====================================================================
// Kernel 2 (fused, single pass, dynamic tiles): scores + exp + stmatrix
// staging + Pt write + invsum.  512 tiles.  (frozen — R15 overlap form)
// =====================================================================
#define FLD   40
#define FSM_FT   0u
#define FSM_G    5120u
#define FSM_GSZ  20480u
#define FSM_ST   46080u
#define FSM_RED  82944u
#define FSM_TOTAL 83968u
#define SM_TILES 512

__global__ __launch_bounds__(256) void fused_sm_kernel()
{
    extern __shared__ __align__(16) char sm[];
    __shared__ unsigned int s_tile;
    const uint32_t smBase = smem_u32(sm);
    float* red = reinterpret_cast<float*>(sm + FSM_RED);

    const int tid  = threadIdx.x;
    const int lane = tid & 31, wid = tid >> 5;
    const int warpM = wid >> 2;
    const int warpN = wid & 3;
    const int qg = lane >> 2, tq = lane & 3;

    const int lm  = lane & 15;
    const int aco = (lane >= 16) ? 8 : 0;
    uint32_t aAddr[2];
#pragma unroll
    for (int mt=0; mt<2; mt++)
        aAddr[mt] = smBase + FSM_FT +
            (uint32_t)(((warpM*32 + mt*16 + lm)*FLD + aco)*2);
    const int bro = (lane & 7) + ((lane >= 16) ? 8 : 0);
    const int bco = (lane & 8) ? 8 : 0;
    uint32_t bOff[4];
#pragma unroll
    for (int p=0; p<4; p++)
        bOff[p] = (uint32_t)(((warpN*64 + p*16 + bro)*FLD + bco)*2);

    const int grow = tid >> 2, gch = tid & 3;
    const uint32_t stLane = smBase + FSM_ST +
        (uint32_t)(((lane & 7) * 72 + ((lane & 8) ? 8 : 0)) * 2);

    const float CEXP  = 0.17677669529663688f * 1.4426950408889634f;
    const float SHIFT = 16.0f * 1.4426950408889634f;

    for (;;) {
        if (tid == 0) s_tile = atomicAdd(&g_ctr_sm, 1u);
        __syncthreads();
        const unsigned int tile = s_tile;
        if (tile >= SM_TILES) return;
        const int z  = (int)(tile >> 6);
        const int n0 = (int)(tile & 63) * 64;

        {
            const int row = tid >> 2, ch = tid & 3;
            CP_ASYNC16(smBase + FSM_FT + (uint32_t)((row*FLD + ch*8)*2),
                       (const char*)&g_fT[z][n0 + row][ch*8]);
        }
        CP_ASYNC_COMMIT();

        float rsum[4];
#pragma unroll
        for (int i=0;i<4;i++) rsum[i] = 0.f;

        {
            const char* src = (const char*)&g_gT[z][0][0];
#pragma unroll
            for (int i=0;i<4;i++)
                CP_ASYNC16(smBase + FSM_G + (uint32_t)(((grow+i*64)*FLD + gch*8)*2),
                           src + (size_t)(grow + i*64)*64 + gch*16);
            CP_ASYNC_COMMIT();
        }
        for (int t = 0; t < 16; ++t) {
            if (t < 15) {
                const uint32_t dst = smBase + FSM_G + (uint32_t)((t+1)&1)*FSM_GSZ;
                const char* src = (const char*)&g_gT[z][(t+1)*256][0];
#pragma unroll
                for (int i=0;i<4;i++)
                    CP_ASYNC16(dst + (uint32_t)(((grow+i*64)*FLD + gch*8)*2),
                               src + (size_t)(grow + i*64)*64 + gch*16);
                CP_ASYNC_COMMIT();
                CP_ASYNC_WAIT_1();
            } else {
                CP_ASYNC_WAIT_0();
            }
            __syncthreads();   // g(t) ready; STSM(t-1) visible

            if (t > 0) {
                const int ch = tid & 7;
#pragma unroll
                for (int i=0;i<8;i++){
                    const int ml = (tid>>3) + i*32;
                    const uint4 v = *reinterpret_cast<const uint4*>(
                        sm + FSM_ST + (uint32_t)((ml*72 + ch*8)*2));
                    *reinterpret_cast<uint4*>(&g_Pt[z][(t-1)*256 + ml][n0 + ch*8]) = v;
                }
            }

            const uint32_t gb = smBase + FSM_G + (uint32_t)(t&1)*FSM_GSZ;
            float acc[2][8][4];
#pragma unroll
            for (int mt=0;mt<2;mt++)
#pragma unroll
                for (int nt=0;nt<8;nt++)
#pragma unroll
                    for (int c=0;c<4;c++) acc[mt][nt][c] = 0.f;

#pragma unroll
            for (int ks = 0; ks < 2; ++ks) {
                uint32_t a[2][4];
#pragma unroll
                for (int mt=0; mt<2; mt++)
                    LDSM_X4(a[mt][0], a[mt][1], a[mt][2], a[mt][3],
                            aAddr[mt] + ks*32);
                uint32_t bb[4][4];
#pragma unroll
                for (int p=0; p<4; p++)
                    LDSM_X4(bb[p][0], bb[p][1], bb[p][2], bb[p][3],
                            gb + bOff[p] + ks*32);
#pragma unroll
                for (int mt=0; mt<2; mt++)
#pragma unroll
                    for (int nt=0; nt<8; nt++) {
                        const uint32_t b0 = bb[nt>>1][(nt&1)*2];
                        const uint32_t b1 = bb[nt>>1][(nt&1)*2+1];
                        MMA_BF16(acc[mt][nt][0], acc[mt][nt][1],
                                 acc[mt][nt][2], acc[mt][nt][3],
                                 a[mt][0], a[mt][1], a[mt][2], a[mt][3], b0, b1);
                    }
            }

            __syncthreads();   // all warps done reading staging(t-1)

#pragma unroll
            for (int mt=0;mt<2;mt++)
#pragma unroll
                for (int nt=0;nt<8;nt++){
                    const float p0 = ex2f(fmaf(acc[mt][nt][0], CEXP, -SHIFT));
                    const float p1 = ex2f(fmaf(acc[mt][nt][1], CEXP, -SHIFT));
                    const float p2 = ex2f(fmaf(acc[mt][nt][2], CEXP, -SHIFT));
                    const float p3 = ex2f(fmaf(acc[mt][nt][3], CEXP, -SHIFT));
                    rsum[mt*2+0] += p0 + p1;
                    rsum[mt*2+1] += p2 + p3;
                    __nv_bfloat162 q0 = __float22bfloat162_rn(make_float2(p0, p1));
                    __nv_bfloat162 q1 = __float22bfloat162_rn(make_float2(p2, p3));
                    const uint32_t addr = stLane +
                        (uint32_t)(((warpN*64 + nt*8)*72 + warpM*32 + mt*16) * 2);
                    STSM_X2_TRANS(addr,
                                  reinterpret_cast<uint32_t&>(q0),
                                  reinterpret_cast<uint32_t&>(q1));
                }
        }

        __syncthreads();
        {
            const int ch = tid & 7;
#pragma unroll
            for (int i=0;i<8;i++){
                const int ml = (tid>>3) + i*32;
                const uint4 v = *reinterpret_cast<const uint4*>(
                    sm + FSM_ST + (uint32_t)((ml*72 + ch*8)*2));
                *reinterpret_cast<uint4*>(&g_Pt[z][15*256 + ml][n0 + ch*8]) = v;
            }
        }

#pragma unroll
        for (int i=0;i<4;i++){
            float v = rsum[i];
            v += __shfl_xor_sync(0xffffffffu, v, 1);
            v += __shfl_xor_sync(0xffffffffu, v, 2);
            rsum[i] = v;
        }
        if (tq == 0) {
#pragma unroll
            for (int i=0;i<4;i++){
                const int r = warpM*32 + (i>>1)*16 + qg + (i&1)*8;
                red[r*4 + warpN] = rsum[i];
            }
        }
        __syncthreads();
        if (warpN == 0 && tq == 0) {
#pragma unroll
            for (int i=0;i<4;i++){
                const int r = warpM*32 + (i>>1)*16 + qg + (i&1)*8;
                const float s = red[r*4+0] + red[r*4+1] + red[r*4+2] + red[r*4+3];
                g_invsum[z][n0 + r] = 1.0f / s;
            }
        }
        __syncthreads();
    }
}

// =====================================================================
// Kernel 3 (dynamic tiles, 256 threads / 8 warps): h projection via HMMA.
// CTA 64(o) x 128(n), warp grid 2(o) x 4(n), warp tile 32x32,
// K = 2 stages of 128.  2 CTAs/SM -> 16 warps/SM.  1024 tiles.
// =====================================================================
#define PH_LDA   136
#define PH_AST   (64*PH_LDA*2)
#define PH_BST   (128*PH_LDA*2)
#define PH_STG   (PH_AST + PH_BST)
#define PH_SMEM  (2*PH_STG)
#define PH_TILES 1024

__global__ void __launch_bounds__(256, 2) proj_h_mma_kernel(
    const float* __restrict__ h1b, const float* __restrict__ h2b)
{
    extern __shared__ char smh[];
    __shared__ unsigned int s_tile;
    const uint32_t smBase = smem_u32(smh);

    const int tid = threadIdx.x;
    const int wid = tid >> 5, lane = tid & 31;

    const int warpO = wid >> 2;          // 0..1 (o, 32 rows)
    const int warpN = wid & 3;           // 0..3 (n, 32 cols)
    const int lm  = lane & 15;
    const int aco = (lane >= 16) ? 8 : 0;
    uint32_t aOff[2];
#pragma unroll
    for (int mt=0; mt<2; mt++)
        aOff[mt] = (uint32_t)(((warpO*32 + mt*16 + lm)*PH_LDA + aco)*2);
    const int bro = (lane & 7) + ((lane >= 16) ? 8 : 0);
    const int bco = (lane & 8) ? 8 : 0;
    uint32_t bOffA[2];
#pragma unroll
    for (int p=0; p<2; p++)
        bOffA[p] = PH_AST + (uint32_t)(((warpN*32 + p*16 + bro)*PH_LDA + bco)*2);

    // loaders: A 64 rows x 4 thr/row (64B each); B 128 rows x 2 thr/row (128B each)
    const int arow = tid >> 2;
    const int acol = (tid & 3) * 64;
    const uint32_t dA = (uint32_t)(arow * (PH_LDA*2) + acol);
    const int brow = tid >> 1;
    const int bhalf = (tid & 1) * 128;
    const uint32_t dB = PH_AST + (uint32_t)(brow * (PH_LDA*2) + bhalf);

    for (;;) {
        if (tid == 0) s_tile = atomicAdd(&g_ctr_ph, 1u);
        __syncthreads();
        const unsigned int tile = s_tile;
        if (tile >= PH_TILES) return;
        const int z     = (int)(tile >> 7);
        const int oBase = (int)((tile >> 5) & 3) * 64;
        const int nBase = (int)(tile & 31) * 128;
        const int br = z >> 2;
        const float* bias = br ? h2b : h1b;

        const char* gA = (const char*)&g_Wb[br][oBase + arow][0] + acol;
        const char* gB = (const char*)&g_Xt[z][nBase + brow][0] + bhalf;

#pragma unroll
        for (int st = 0; st < 2; ++st) {
            const uint32_t slot = smBase + (uint32_t)st * PH_STG;
#pragma unroll
            for (int j=0;j<4;j++) CP_ASYNC16(slot + dA + j*16, gA + st*256 + j*16);
#pragma unroll
            for (int j=0;j<8;j++) CP_ASYNC16(slot + dB + j*16, gB + st*256 + j*16);
            CP_ASYNC_COMMIT();
        }

        float acc[2][4][4];
#pragma unroll
        for (int i=0;i<2;i++)
#pragma unroll
            for (int j=0;j<4;j++)
#pragma unroll
                for (int k=0;k<4;k++) acc[i][j][k] = 0.f;

#pragma unroll
        for (int st = 0; st < 2; ++st) {
            if (st == 0) CP_ASYNC_WAIT_1(); else CP_ASYNC_WAIT_0();
            __syncthreads();
            const uint32_t slot = smBase + (uint32_t)st * PH_STG;
#pragma unroll
            for (int ks = 0; ks < 8; ++ks) {
                uint32_t a[2][4];
#pragma unroll
                for (int mt=0; mt<2; mt++)
                    LDSM_X4(a[mt][0], a[mt][1], a[mt][2], a[mt][3],
                            slot + aOff[mt] + ks*32);
                uint32_t bb[2][4];
#pragma unroll
                for (int p=0; p<2; p++)
                    LDSM_X4(bb[p][0], bb[p][1], bb[p][2], bb[p][3],
                            slot + bOffA[p] + ks*32);
#pragma unroll
                for (int mt=0; mt<2; mt++)
#pragma unroll
                    for (int nt=0; nt<4; nt++) {
                        const uint32_t b0 = bb[nt>>1][(nt&1)*2];
                        const uint32_t b1 = bb[nt>>1][(nt&1)*2+1];
                        MMA_BF16(acc[mt][nt][0], acc[mt][nt][1],
                                 acc[mt][nt][2], acc[mt][nt][3],
                                 a[mt][0], a[mt][1], a[mt][2], a[mt][3], b0, b1);
                    }
            }
        }

        const int g  = lane >> 2;
        const int tq = lane & 3;
#pragma unroll
        for (int mt=0; mt<2; mt++) {
            const int row0 = oBase + warpO*32 + mt*16 + g;
            const float bv0 = bias[row0];
            const float bv8 = bias[row0 + 8];
#pragma unroll
            for (int nt=0; nt<4; nt++) {
                const int col = nBase + warpN*32 + nt*8 + tq*2;
                const float2 iv = *reinterpret_cast<const float2*>(&g_invsum[z][col]);
                {
                    const float v0 = (acc[mt][nt][0] + bv0) * iv.x;
                    const float v1 = (acc[mt][nt][1] + bv0) * iv.y;
                    __nv_bfloat162 pk = __float22bfloat162_rn(make_float2(v0, v1));
                    *reinterpret_cast<uint32_t*>(&g_Hb[z][row0][col]) =
                        reinterpret_cast<uint32_t&>(pk);
                }
                {
                    const float v0 = (acc[mt][nt][2] + bv8) * iv.x;
                    const float v1 = (acc[mt][nt][3] + bv8) * iv.y;
                    __nv_bfloat162 pk = __float22bfloat162_rn(make_float2(v0, v1));
                    *reinterpret_cast<uint32_t*>(&g_Hb[z][row0 + 8][col]) =
                        reinterpret_cast<uint32_t&>(pk);
                }
            }
        }
    }
}

// =====================================================================
// Kernel 4 (dynamic tiles): out[z] = gamma*(H'@P') + x.  512 tiles.
// (frozen, c-fastest order)
// =====================================================================
#define BK      64
#define LDSS    72
#define STGB    (128*LDSS*2)
#define NSTG    3
#define OUT_SMEM (NSTG*2*STGB)
#define OUT_TILES 512

__global__ void __launch_bounds__(256, 2) out_mma_kernel(
    const float* __restrict__ x1, const float* __restrict__ x2,
    const float* __restrict__ gamma1, const float* __restrict__ gamma2,
    float* __restrict__ out)
{
    extern __shared__ char smo[];
    __shared__ unsigned int s_tile;
    const uint32_t smBase = smem_u32(smo);

    const int tid = threadIdx.x;
    const int wid = tid >> 5, lane = tid & 31;

    const int lrow = tid >> 1;
    const int lcol = (tid & 1) * 32;
    const uint32_t ldOff = (uint32_t)((lrow*LDSS + lcol)*2);

    const int warpM = wid >> 2;
    const int warpN = wid & 3;
    const int lm  = lane & 15;
    const int aco = (lane >= 16) ? 8 : 0;
    uint32_t aOff[4];
#pragma unroll
    for (int mt=0; mt<4; mt++)
        aOff[mt] = (uint32_t)(((warpM*64 + mt*16 + lm)*LDSS + aco)*2);
    const int bro = (lane & 7) + ((lane >= 16) ? 8 : 0);
    const int bco = (lane & 8) ? 8 : 0;
    uint32_t bOff[2];
#pragma unroll
    for (int p=0; p<2; p++)
        bOff[p] = (uint32_t)(((warpN*32 + p*16 + bro)*LDSS + bco)*2) + STGB;

    for (;;) {
        if (tid == 0) s_tile = atomicAdd(&g_ctr_out, 1u);
        __syncthreads();
        const unsigned int tile = s_tile;
        if (tile >= OUT_TILES) return;
        const int z     = (int)(tile >> 6);
        const int mBase = (int)((tile >> 1) & 31) * 128;
        const int cBase = (int)(tile & 1) * 128;
        const int br = z >> 2, b = z & 3;
        const float* X = (br ? x2 : x1) + (size_t)b * CH * NPIX;
        const float gamma = (br ? gamma2 : gamma1)[0];

        const char* gAp = (const char*)(&g_Hb[z][cBase + lrow][lcol]);
        const char* gBp = (const char*)(&g_Pt[z][mBase + lrow][lcol]);

        float acc[4][4][4];
#pragma unroll
        for (int i=0;i<4;i++)
#pragma unroll
            for (int j=0;j<4;j++)
#pragma unroll
                for (int k=0;k<4;k++) acc[i][j][k] = 0.f;

#pragma unroll
        for (int st=0; st<2; ++st) {
            const uint32_t slot = smBase + (uint32_t)st * (2*STGB);
            const char* sa = gAp + (size_t)st * (BK*2);
            const char* sb = gBp + (size_t)st * (BK*2);
#pragma unroll
            for (int j=0;j<4;j++) CP_ASYNC16(slot + ldOff + j*16, sa + j*16);
#pragma unroll
            for (int j=0;j<4;j++) CP_ASYNC16(slot + STGB + ldOff + j*16, sb + j*16);
            CP_ASYNC_COMMIT();
        }

        int slotC = 0;
        int slotP = 2;
        for (int it = 0; it < NPIX/BK; ++it) {
            CP_ASYNC_WAIT_1();
            __syncthreads();

            if (it + 2 < NPIX/BK) {
                const uint32_t slot = smBase + (uint32_t)slotP * (2*STGB);
                const char* sa = gAp + (size_t)(it+2) * (BK*2);
                const char* sb = gBp + (size_t)(it+2) * (BK*2);
#pragma unroll
                for (int j=0;j<4;j++) CP_ASYNC16(slot + ldOff + j*16, sa + j*16);
#pragma unroll
                for (int j=0;j<4;j++) CP_ASYNC16(slot + STGB + ldOff + j*16, sb + j*16);
            }
            CP_ASYNC_COMMIT();

            const uint32_t sb = smBase + (uint32_t)slotC * (2*STGB);
#pragma unroll
            for (int ks = 0; ks < 4; ++ks) {
                uint32_t a[4][4];
#pragma unroll
                for (int mt=0; mt<4; mt++)
                    LDSM_X4(a[mt][0], a[mt][1], a[mt][2], a[mt][3],
                            sb + aOff[mt] + ks*32);
                uint32_t bb[2][4];
#pragma unroll
                for (int p=0; p<2; p++)
                    LDSM_X4(bb[p][0], bb[p][1], bb[p][2], bb[p][3],
                            sb + bOff[p] + ks*32);
#pragma unroll
                for (int mt=0; mt<4; mt++)
#pragma unroll
                    for (int nt=0; nt<4; nt++) {
                        const uint32_t b0 = bb[nt>>1][(nt&1)*2];
                        const uint32_t b1 = bb[nt>>1][(nt&1)*2+1];
                        MMA_BF16(acc[mt][nt][0], acc[mt][nt][1],
                                 acc[mt][nt][2], acc[mt][nt][3],
                                 a[mt][0], a[mt][1], a[mt][2], a[mt][3], b0, b1);
                    }
            }

            slotC = (slotC == 2) ? 0 : slotC + 1;
            slotP = (slotP == 2) ? 0 : slotP + 1;
        }

        const int g  = lane >> 2;
        const int tq = lane & 3;
        float* Cz = out + (size_t)z * CH * NPIX;
#pragma unroll
        for (int mt=0; mt<4; mt++) {
            const int row = cBase + warpM*64 + mt*16 + g;
#pragma unroll
            for (int nt=0; nt<4; nt++) {
                const int col = mBase + warpN*32 + nt*8 + tq*2;
                {
                    const float2 xv = *reinterpret_cast<const float2*>(
                        &X[(size_t)row*NPIX + col]);
                    float2 o;
                    o.x = fmaf(gamma, acc[mt][nt][0], xv.x);
                    o.y = fmaf(gamma, acc[mt][nt][1], xv.y);
                    *reinterpret_cast<float2*>(&Cz[(size_t)row*NPIX + col]) = o;
                }
                {
                    const float2 xv = *reinterpret_cast<const float2*>(
                        &X[(size_t)(row+8)*NPIX + col]);
                    float2 o;
                    o.x = fmaf(gamma, acc[mt][nt][2], xv.x);
                    o.y = fmaf(gamma, acc[mt][nt][3], xv.y);
                    *reinterpret_cast<float2*>(&Cz[(size_t)(row+8)*NPIX + col]) = o;
                }
            }
        }
    }
}

// =====================================================================
extern "C" void kernel_launch(void* const* d_in, const int* in_sizes, int n_in,
                              void* d_out, int out_size)
{
    const float* x1     = (const float*)d_in[0];
    const float* x2     = (const float*)d_in[1];
    const float* f_w    = (const float*)d_in[2];
    const float* f_b    = (const float*)d_in[3];
    const float* g_w    = (const float*)d_in[4];
    const float* g_b    = (const float*)d_in[5];
    const float* h1_w   = (const float*)d_in[6];
    const float* h1_b   = (const float*)d_in[7];
    const float* h2_w   = (const float*)d_in[8];
    const float* h2_b   = (const float*)d_in[9];
    const float* gamma1 = (const float*)d_in[10];
    const float* gamma2 = (const float*)d_in[11];
    float* out = (float*)d_out;

    cudaFuncSetAttribute(proj_fg_mma_kernel,
                         cudaFuncAttributeMaxDynamicSharedMemorySize, FG_SMEM);
    cudaFuncSetAttribute(fused_sm_kernel,
                         cudaFuncAttributeMaxDynamicSharedMemorySize, FSM_TOTAL);
    cudaFuncSetAttribute(proj_h_mma_kernel,
                         cudaFuncAttributeMaxDynamicSharedMemorySize, PH_SMEM);
    cudaFuncSetAttribute(out_mma_kernel,
                         cudaFuncAttributeMaxDynamicSharedMemorySize, OUT_SMEM);

    prep_kernel       <<<XT_BLKS + WC_BLKS, 256>>>(
        x1, x2, f_w, g_w, h1_w, h2_w);
    proj_fg_mma_kernel<<<dim3(32, NZ), 128, FG_SMEM>>>(f_b, g_b);
    fused_sm_kernel   <<<dim3(64, NZ), 256, FSM_TOTAL>>>();
    proj_h_mma_kernel <<<dim3(32, 4, NZ), 256, PH_SMEM>>>(h1_b, h2_b);
    out_mma_kernel    <<<dim3(32, 2, NZ), 256, OUT_SMEM>>>(x1, x2, gamma1, gamma2, out);
}